// round 2
// baseline (speedup 1.0000x reference)
#include <cuda_runtime.h>
#include <math.h>

// ---------------------------------------------------------------------------
// CodeShellAttention: fp32 baseline
//   1) rope_table_kernel : cos/sin tables (double-precision math)
//   2) sgemm_bias_rope   : qkv = X @ Wqkv + bqkv, RoPE fused in epilogue
//   3) flash_kernel      : causal GQA flash attention (fp32, online softmax)
//   4) sgemm_bias_rope   : out = attn @ Wproj + bproj (rope disabled)
// ---------------------------------------------------------------------------

#define S_LEN  2048
#define HID    4096
#define NH     32
#define NKV    8
#define HD     128
#define QKV_N  6144      // HID + 2*KV_DIM
#define HALF   64        // HD/2

__device__ float g_qkv[S_LEN * QKV_N];   // 50.3 MB scratch
__device__ float g_attn[S_LEN * HID];    // 33.5 MB scratch
__device__ float g_cos[S_LEN * HALF];
__device__ float g_sin[S_LEN * HALF];

// --------------------------- RoPE tables -----------------------------------
__global__ void rope_table_kernel(const int* __restrict__ positions)
{
    int i = blockIdx.x * blockDim.x + threadIdx.x;
    if (i >= S_LEN * HALF) return;
    int m = i >> 6;
    int d = i & 63;
    double p    = (double)positions[m];
    double invf = pow(10000.0, -((double)d) / 64.0);
    double a    = p * invf;
    g_cos[i] = (float)cos(a);
    g_sin[i] = (float)sin(a);
}

// --------------------------- SGEMM + bias (+RoPE) ---------------------------
// C[M,N] = A[M,K] @ B[K,N] + bias[N];  128x128 tile, TK=8, 256 thr, 8x8/thread.
// Column mapping n = bn + tx + 16*j puts (d, d+64) RoPE pairs in one thread.
__global__ __launch_bounds__(256)
void sgemm_bias_rope(const float* __restrict__ A, const float* __restrict__ B,
                     const float* __restrict__ bias, float* __restrict__ C,
                     int N, int K, int rope_blocks)
{
    __shared__ float As[8][132];   // padded: conflict-free transposed stores
    __shared__ float Bs[8][128];

    const int tid  = threadIdx.x;
    const int tx   = tid & 15, ty = tid >> 4;
    const int bm   = blockIdx.y * 128;
    const int bn   = blockIdx.x * 128;
    const int arow = tid >> 1,  acol = (tid & 1) << 2;
    const int brow = tid >> 5,  bcol = (tid & 31) << 2;

    const float* Ap = A + (size_t)(bm + arow) * K + acol;
    const float* Bp = B + (size_t)brow * N + bn + bcol;

    float acc[8][8];
#pragma unroll
    for (int i = 0; i < 8; i++)
#pragma unroll
        for (int j = 0; j < 8; j++) acc[i][j] = 0.f;

    for (int k0 = 0; k0 < K; k0 += 8) {
        float4 av = *(const float4*)(Ap + k0);
        float4 bv = *(const float4*)(Bp + (size_t)k0 * N);
        As[acol + 0][arow] = av.x;
        As[acol + 1][arow] = av.y;
        As[acol + 2][arow] = av.z;
        As[acol + 3][arow] = av.w;
        *(float4*)&Bs[brow][bcol] = bv;
        __syncthreads();
#pragma unroll
        for (int kk = 0; kk < 8; kk++) {
            float a[8], b[8];
#pragma unroll
            for (int i = 0; i < 8; i++) a[i] = As[kk][ty + 16 * i];
#pragma unroll
            for (int j = 0; j < 8; j++) b[j] = Bs[kk][tx + 16 * j];
#pragma unroll
            for (int i = 0; i < 8; i++)
#pragma unroll
                for (int j = 0; j < 8; j++) acc[i][j] += a[i] * b[j];
        }
        __syncthreads();
    }

    const bool rope = ((int)blockIdx.x < rope_blocks);
#pragma unroll
    for (int i = 0; i < 8; i++) {
        const int m = bm + ty + 16 * i;
        float v[8];
#pragma unroll
        for (int j = 0; j < 8; j++) v[j] = acc[i][j] + bias[bn + tx + 16 * j];
        if (rope) {
#pragma unroll
            for (int j = 0; j < 4; j++) {
                const int d = tx + 16 * j;            // 0..63 within the head
                const float c  = g_cos[m * HALF + d];
                const float s  = g_sin[m * HALF + d];
                const float x1 = v[j], x2 = v[j + 4]; // pair d and d+64
                v[j]     = x1 * c - x2 * s;
                v[j + 4] = x2 * c + x1 * s;
            }
        }
#pragma unroll
        for (int j = 0; j < 8; j++)
            C[(size_t)m * N + bn + tx + 16 * j] = v[j];
    }
}

// --------------------------- Flash attention --------------------------------
#define KPAD 130   // row pad for Q/K/V tiles: bank = (2r + c) % 32, conflict-free
#define SSTR 65    // S tile row stride

__global__ __launch_bounds__(256)
void flash_kernel()
{
    extern __shared__ float sm[];
    float* Qs   = sm;                  // 64 x KPAD
    float* Ks   = Qs + 64 * KPAD;      // 64 x KPAD
    float* Vs   = Ks + 64 * KPAD;      // 64 x KPAD
    float* Ss   = Vs + 64 * KPAD;      // 64 x SSTR
    float* rowm = Ss + 64 * SSTR;      // 64
    float* rowl = rowm + 64;           // 64
    float* rowa = rowl + 64;           // 64

    const int qt   = blockIdx.x;       // q tile (64 rows)
    const int h    = blockIdx.y;       // head
    const int kvh  = h >> 2;           // GQA: 4 q-heads per kv-head
    const int tid  = threadIdx.x;
    const int lane = tid & 31;
    const int warp = tid >> 5;
    const int tx   = tid & 15, ty = tid >> 4;

    const float scale = 0.08838834764831845f;  // 1/sqrt(128)

    // load Q tile: warp w loads row w+8*it, lanes cover 128 floats as float4
    const float* qbase = g_qkv + (size_t)(qt * 64) * QKV_N + h * HD;
#pragma unroll
    for (int it = 0; it < 8; it++) {
        int r = warp + 8 * it;
        float4 q4 = *(const float4*)(qbase + (size_t)r * QKV_N + lane * 4);
        float* dst = Qs + r * KPAD + lane * 4;
        dst[0] = q4.x; dst[1] = q4.y; dst[2] = q4.z; dst[3] = q4.w;
    }
    if (tid < 64) { rowm[tid] = -INFINITY; rowl[tid] = 0.f; }

    float o[4][8];
#pragma unroll
    for (int i = 0; i < 4; i++)
#pragma unroll
        for (int j = 0; j < 8; j++) o[i][j] = 0.f;

    __syncthreads();

    for (int kt = 0; kt <= qt; kt++) {
        // load K/V tiles
        const float* kbase = g_qkv + (size_t)(kt * 64) * QKV_N + HID + kvh * HD;
        const float* vbase = kbase + NKV * HD;
#pragma unroll
        for (int it = 0; it < 8; it++) {
            int r = warp + 8 * it;
            float4 k4 = *(const float4*)(kbase + (size_t)r * QKV_N + lane * 4);
            float4 v4 = *(const float4*)(vbase + (size_t)r * QKV_N + lane * 4);
            float* kd = Ks + r * KPAD + lane * 4;
            kd[0] = k4.x; kd[1] = k4.y; kd[2] = k4.z; kd[3] = k4.w;
            float* vd = Vs + r * KPAD + lane * 4;
            vd[0] = v4.x; vd[1] = v4.y; vd[2] = v4.z; vd[3] = v4.w;
        }
        __syncthreads();

        // S = Q @ K^T : 4x4 per thread (rows ty+16i, cols tx+16j)
        float s[4][4];
#pragma unroll
        for (int i = 0; i < 4; i++)
#pragma unroll
            for (int j = 0; j < 4; j++) s[i][j] = 0.f;
#pragma unroll 8
        for (int d = 0; d < HD; d++) {
            float a[4], b[4];
#pragma unroll
            for (int i = 0; i < 4; i++) a[i] = Qs[(ty + 16 * i) * KPAD + d];
#pragma unroll
            for (int j = 0; j < 4; j++) b[j] = Ks[(tx + 16 * j) * KPAD + d];
#pragma unroll
            for (int i = 0; i < 4; i++)
#pragma unroll
                for (int j = 0; j < 4; j++) s[i][j] += a[i] * b[j];
        }
        // scale + causal mask, store to Ss
        const bool diag = (kt == qt);
#pragma unroll
        for (int i = 0; i < 4; i++) {
            const int qr = ty + 16 * i;
#pragma unroll
            for (int j = 0; j < 4; j++) {
                const int kc = tx + 16 * j;
                float sv = s[i][j] * scale;
                if (diag && kc > qr) sv = -INFINITY;
                Ss[qr * SSTR + kc] = sv;
            }
        }
        __syncthreads();

        // online softmax: 4 threads per row
        {
            const int r = tid >> 2, part = tid & 3;
            float mloc = -INFINITY;
#pragma unroll
            for (int t = 0; t < 16; t++)
                mloc = fmaxf(mloc, Ss[r * SSTR + part * 16 + t]);
            mloc = fmaxf(mloc, __shfl_xor_sync(0xffffffffu, mloc, 1));
            mloc = fmaxf(mloc, __shfl_xor_sync(0xffffffffu, mloc, 2));
            const float mold = rowm[r];
            const float mnew = fmaxf(mold, mloc);
            float suml = 0.f;
#pragma unroll
            for (int t = 0; t < 16; t++) {
                const int idx = r * SSTR + part * 16 + t;
                float p = expf(Ss[idx] - mnew);
                Ss[idx] = p;
                suml += p;
            }
            suml += __shfl_xor_sync(0xffffffffu, suml, 1);
            suml += __shfl_xor_sync(0xffffffffu, suml, 2);
            if (part == 0) {
                const float alpha = expf(mold - mnew);  // 0 on first tile
                rowa[r] = alpha;
                rowm[r] = mnew;
                rowl[r] = rowl[r] * alpha + suml;
            }
        }
        __syncthreads();

        // O = O*alpha + P @ V : 4x8 per thread (rows ty+16i, cols tx+16j)
#pragma unroll
        for (int i = 0; i < 4; i++) {
            const float al = rowa[ty + 16 * i];
#pragma unroll
            for (int j = 0; j < 8; j++) o[i][j] *= al;
        }
#pragma unroll 8
        for (int c = 0; c < 64; c++) {
            float a[4], b[8];
#pragma unroll
            for (int i = 0; i < 4; i++) a[i] = Ss[(ty + 16 * i) * SSTR + c];
#pragma unroll
            for (int j = 0; j < 8; j++) b[j] = Vs[c * KPAD + tx + 16 * j];
#pragma unroll
            for (int i = 0; i < 4; i++)
#pragma unroll
                for (int j = 0; j < 8; j++) o[i][j] += a[i] * b[j];
        }
        __syncthreads();  // protect Ks/Vs/Ss before next iteration's loads
    }

    // finalize: divide by l, write to g_attn
#pragma unroll
    for (int i = 0; i < 4; i++) {
        const int ry  = ty + 16 * i;
        const float inv = 1.0f / rowl[ry];
        const int m   = qt * 64 + ry;
#pragma unroll
        for (int j = 0; j < 8; j++)
            g_attn[(size_t)m * HID + h * HD + tx + 16 * j] = o[i][j] * inv;
    }
}

// --------------------------- launch ------------------------------------------
extern "C" void kernel_launch(void* const* d_in, const int* in_sizes, int n_in,
                              void* d_out, int out_size)
{
    (void)in_sizes; (void)n_in; (void)out_size;
    const int*   positions = (const int*)  d_in[0];
    const float* X         = (const float*)d_in[1];
    const float* Wqkv      = (const float*)d_in[2];
    const float* bqkv      = (const float*)d_in[3];
    const float* Wproj     = (const float*)d_in[4];
    const float* bproj     = (const float*)d_in[5];
    float* out = (float*)d_out;

    float *qkv_p, *attn_p;
    cudaGetSymbolAddress((void**)&qkv_p,  g_qkv);
    cudaGetSymbolAddress((void**)&attn_p, g_attn);

    // 1) RoPE tables
    rope_table_kernel<<<(S_LEN * HALF + 255) / 256, 256>>>(positions);

    // 2) QKV GEMM + bias + fused RoPE (first 40 column-tiles = q & k heads)
    {
        dim3 grid(QKV_N / 128, S_LEN / 128);
        sgemm_bias_rope<<<grid, 256>>>(X, Wqkv, bqkv, qkv_p, QKV_N, HID, 40);
    }

    // 3) Flash attention
    {
        const int smem = (3 * 64 * KPAD + 64 * SSTR + 3 * 64) * (int)sizeof(float);
        cudaFuncSetAttribute(flash_kernel,
                             cudaFuncAttributeMaxDynamicSharedMemorySize, smem);
        dim3 grid(S_LEN / 64, NH);
        flash_kernel<<<grid, 256, smem>>>();
    }

    // 4) Output projection
    {
        dim3 grid(HID / 128, S_LEN / 128);
        sgemm_bias_rope<<<grid, 256>>>(attn_p, Wproj, bproj, out, HID, HID, 0);
    }
}

// round 4
// speedup vs baseline: 2.3572x; 2.3572x over previous
#include <cuda_runtime.h>
#include <cuda_bf16.h>
#include <math.h>
#include <stdint.h>

// ---------------------------------------------------------------------------
// CodeShellAttention round 4:
//   GEMMs on mma.sync (HMMA bf16 hi/lo split, fp32 accum) — tcgen05 PTX is
//   rejected by this harness (.target sm_103 without 'a').
//   Flash attention: fp32 (next round's target).
// ---------------------------------------------------------------------------

#define S_LEN  2048
#define HID    4096
#define NH     32
#define NKV    8
#define HD     128
#define QKV_N  6144
#define HALF   64

__device__ float g_qkv[S_LEN * QKV_N];
__device__ float g_attn[S_LEN * HID];
__device__ float g_cos[S_LEN * HALF];
__device__ float g_sin[S_LEN * HALF];

// ========================= helpers =========================================
__device__ __forceinline__ uint32_t smem_u32(const void* p) {
    uint32_t a;
    asm("{ .reg .u64 t; cvta.to.shared.u64 t, %1; cvt.u32.u64 %0, t; }"
        : "=r"(a) : "l"(p));
    return a;
}

__device__ __forceinline__ void ldsm4(uint32_t* r, uint32_t addr) {
    asm volatile("ldmatrix.sync.aligned.m8n8.x4.shared.b16 {%0,%1,%2,%3}, [%4];"
                 : "=r"(r[0]), "=r"(r[1]), "=r"(r[2]), "=r"(r[3]) : "r"(addr));
}

__device__ __forceinline__ void mma16816(float* d, const uint32_t* a,
                                         const uint32_t* b) {
    asm volatile(
        "mma.sync.aligned.m16n8k16.row.col.f32.bf16.bf16.f32 "
        "{%0,%1,%2,%3}, {%4,%5,%6,%7}, {%8,%9}, {%0,%1,%2,%3};"
        : "+f"(d[0]), "+f"(d[1]), "+f"(d[2]), "+f"(d[3])
        : "r"(a[0]), "r"(a[1]), "r"(a[2]), "r"(a[3]), "r"(b[0]), "r"(b[1]));
}

// truncation split of two floats into packed hi-bf16x2 / lo-bf16x2
__device__ __forceinline__ void split2(float x, float y, uint32_t& hi, uint32_t& lo)
{
    uint32_t bx = __float_as_uint(x), by = __float_as_uint(y);
    hi = __byte_perm(bx, by, 0x7632);
    float hx = __uint_as_float(bx & 0xFFFF0000u);
    float hy = __uint_as_float(by & 0xFFFF0000u);
    __nv_bfloat162 l = __floats2bfloat162_rn(x - hx, y - hy);
    lo = *reinterpret_cast<uint32_t*>(&l);
}

#define STS64(a, v0, v1) \
    asm volatile("st.shared.v2.u32 [%0], {%1, %2};" :: "r"(a), "r"(v0), "r"(v1) : "memory")
#define STS128(a, v0, v1, v2, v3) \
    asm volatile("st.shared.v4.u32 [%0], {%1, %2, %3, %4};" \
                 :: "r"(a), "r"(v0), "r"(v1), "r"(v2), "r"(v3) : "memory")

// ========================= RoPE tables =====================================
__global__ void rope_table_kernel(const int* __restrict__ positions)
{
    int i = blockIdx.x * blockDim.x + threadIdx.x;
    if (i >= S_LEN * HALF) return;
    int m = i >> 6;
    int d = i & 63;
    double p    = (double)positions[m];
    double invf = pow(10000.0, -((double)d) / 64.0);
    double a    = p * invf;
    g_cos[i] = (float)cos(a);
    g_sin[i] = (float)sin(a);
}

// ========================= HMMA GEMM =======================================
// C[M,N] = A[M,K] @ B[K,N] + bias (+RoPE). Block 128x128, 8 warps (2Mx4N),
// warp tile 64x32, K-chunk 32. Smem tiles hold packed bf16: row layout
// [hi k0..31 | lo k0..31 | pad], row stride 144 B. Double buffered.
#define RSTR   144                    // bytes per smem tile row
#define TILEB  (128 * RSTR)           // 18432 per operand tile
#define STAGEB (2 * TILEB)            // 36864 per stage (A + B)
#define SMEM_GEMM (2 * STAGEB)        // 73728
#define ESTR   132                    // epilogue float stride

__global__ __launch_bounds__(256, 1)
void hmma_gemm(const float* __restrict__ A, const float* __restrict__ B,
               const float* __restrict__ bias, float* __restrict__ C,
               int N, int K, int rope_limit)
{
    extern __shared__ char smem[];
    const uint32_t sb = smem_u32(smem);

    const int tid  = threadIdx.x;
    const int lane = tid & 31;
    const int warp = tid >> 5;
    const int wm   = warp >> 2;          // 0..1  (64 rows each)
    const int wn   = warp & 3;           // 0..3  (32 cols each)
    const int bm   = blockIdx.y * 128;
    const int bn   = blockIdx.x * 128;

    // global load indices
    const int arow = tid >> 3;           // 0..31
    const int acol = (tid & 7) * 4;      // 0..28
    const int bkg  = tid >> 6;           // 0..3 (k-group of 8)
    const int bn2  = (tid & 63) * 2;     // 0..126

    const float* Aptr = A + (size_t)(bm + arow) * K + acol;
    const float* Bptr = B + (size_t)(bkg * 8) * N + bn + bn2;

    float acc[4][4][4];
#pragma unroll
    for (int i = 0; i < 4; i++)
#pragma unroll
        for (int j = 0; j < 4; j++)
#pragma unroll
            for (int t = 0; t < 4; t++) acc[i][j][t] = 0.f;

    const int nchunk = K >> 5;
    float4 areg[4];
    float2 breg[8];

    // ---- prologue: load chunk 0 ----
#pragma unroll
    for (int i = 0; i < 4; i++)
        areg[i] = *(const float4*)(Aptr + (size_t)(32 * i) * K);
#pragma unroll
    for (int i = 0; i < 8; i++)
        breg[i] = *(const float2*)(Bptr + (size_t)i * N);

    // store chunk into stage s
    auto sts_chunk = [&](int s) {
        const uint32_t stA = sb + s * STAGEB;
        const uint32_t stB = stA + TILEB;
#pragma unroll
        for (int i = 0; i < 4; i++) {
            uint32_t h01, l01, h23, l23;
            split2(areg[i].x, areg[i].y, h01, l01);
            split2(areg[i].z, areg[i].w, h23, l23);
            const uint32_t off = (uint32_t)((arow + 32 * i) * RSTR + acol * 2);
            STS64(stA + off,      h01, h23);
            STS64(stA + off + 64, l01, l23);
        }
        uint32_t hx[4], lx[4], hy[4], ly[4];
#pragma unroll
        for (int j = 0; j < 4; j++) {
            split2(breg[2 * j].x, breg[2 * j + 1].x, hx[j], lx[j]);
            split2(breg[2 * j].y, breg[2 * j + 1].y, hy[j], ly[j]);
        }
        const uint32_t o0 = (uint32_t)(bn2 * RSTR + bkg * 16);
        const uint32_t o1 = o0 + RSTR;
        STS128(stB + o0,      hx[0], hx[1], hx[2], hx[3]);
        STS128(stB + o0 + 64, lx[0], lx[1], lx[2], lx[3]);
        STS128(stB + o1,      hy[0], hy[1], hy[2], hy[3]);
        STS128(stB + o1 + 64, ly[0], ly[1], ly[2], ly[3]);
    };

    sts_chunk(0);
    __syncthreads();

    // ldmatrix base offsets (per-lane constant parts)
    // A: row = wm*64 + mt*16 + (lane&15); bytecol = ks*32 + (lane>>4)*16 (+64 lo)
    const uint32_t a_l = (uint32_t)((lane & 15) * RSTR + (lane >> 4) * 16);
    // B: n = wn*32 + np*16 + (lane&7) + ((lane>>4)&1)*8; bytecol = ks*32 + ((lane>>3)&1)*16
    const uint32_t b_l = (uint32_t)(((lane & 7) + ((lane >> 4) & 1) * 8) * RSTR
                                    + ((lane >> 3) & 1) * 16);

    for (int c = 0; c < nchunk; c++) {
        const int s = c & 1;
        const uint32_t stA = sb + s * STAGEB;
        const uint32_t stB = stA + TILEB;

        // prefetch next chunk into regs
        if (c + 1 < nchunk) {
            const int k0 = (c + 1) << 5;
#pragma unroll
            for (int i = 0; i < 4; i++)
                areg[i] = *(const float4*)(Aptr + (size_t)(32 * i) * K + k0);
#pragma unroll
            for (int i = 0; i < 8; i++)
                breg[i] = *(const float2*)(Bptr + (size_t)(k0 + i) * N);
        }

        // compute: 2 k-steps of 16
#pragma unroll
        for (int ks = 0; ks < 2; ks++) {
            uint32_t ah[4][4], al[4][4], bh[4][2], bl[4][2];
#pragma unroll
            for (int mt = 0; mt < 4; mt++) {
                const uint32_t base = stA + a_l
                    + (uint32_t)((wm * 64 + mt * 16) * RSTR + ks * 32);
                ldsm4(ah[mt], base);
                ldsm4(al[mt], base + 64);
            }
#pragma unroll
            for (int np = 0; np < 2; np++) {
                const uint32_t base = stB + b_l
                    + (uint32_t)((wn * 32 + np * 16) * RSTR + ks * 32);
                uint32_t th[4], tl[4];
                ldsm4(th, base);
                ldsm4(tl, base + 64);
                bh[2 * np][0] = th[0]; bh[2 * np][1] = th[1];
                bh[2 * np + 1][0] = th[2]; bh[2 * np + 1][1] = th[3];
                bl[2 * np][0] = tl[0]; bl[2 * np][1] = tl[1];
                bl[2 * np + 1][0] = tl[2]; bl[2 * np + 1][1] = tl[3];
            }
#pragma unroll
            for (int mt = 0; mt < 4; mt++)
#pragma unroll
                for (int nt = 0; nt < 4; nt++) {
                    mma16816(acc[mt][nt], ah[mt], bh[nt]);
                    mma16816(acc[mt][nt], ah[mt], bl[nt]);
                    mma16816(acc[mt][nt], al[mt], bh[nt]);
                }
        }

        if (c + 1 < nchunk) {
            sts_chunk((c + 1) & 1);
            __syncthreads();
        }
    }

    // ---- epilogue: frags -> smem f32, then bias (+RoPE) -> global ----
    __syncthreads();
    float* Ss = (float*)smem;
    {
        const int r0 = wm * 64 + (lane >> 2);
        const int c0 = wn * 32 + (lane & 3) * 2;
#pragma unroll
        for (int mt = 0; mt < 4; mt++)
#pragma unroll
            for (int nt = 0; nt < 4; nt++) {
                const int r = r0 + mt * 16;
                const int cc = c0 + nt * 8;
                *(float2*)&Ss[r * ESTR + cc] =
                    make_float2(acc[mt][nt][0], acc[mt][nt][1]);
                *(float2*)&Ss[(r + 8) * ESTR + cc] =
                    make_float2(acc[mt][nt][2], acc[mt][nt][3]);
            }
    }
    __syncthreads();

    {
        const int tx = tid & 15, ty = tid >> 4;
        const bool rope = (bn < rope_limit);
#pragma unroll
        for (int i = 0; i < 8; i++) {
            const int row = ty + 16 * i;
            const int m   = bm + row;
            float v[8];
#pragma unroll
            for (int j = 0; j < 8; j++)
                v[j] = Ss[row * ESTR + tx + 16 * j] + bias[bn + tx + 16 * j];
            if (rope) {
#pragma unroll
                for (int j = 0; j < 4; j++) {
                    const int d = tx + 16 * j;
                    const float cc = g_cos[m * HALF + d];
                    const float ssn = g_sin[m * HALF + d];
                    const float x1 = v[j], x2 = v[j + 4];
                    v[j]     = x1 * cc - x2 * ssn;
                    v[j + 4] = x2 * cc + x1 * ssn;
                }
            }
#pragma unroll
            for (int j = 0; j < 8; j++)
                C[(size_t)m * N + bn + tx + 16 * j] = v[j];
        }
    }
}

// ========================= Flash attention (fp32) ===========================
#define KPAD 130
#define SSTR 65

__global__ __launch_bounds__(256)
void flash_kernel()
{
    extern __shared__ float sm[];
    float* Qs   = sm;
    float* Ks   = Qs + 64 * KPAD;
    float* Vs   = Ks + 64 * KPAD;
    float* Ss   = Vs + 64 * KPAD;
    float* rowm = Ss + 64 * SSTR;
    float* rowl = rowm + 64;
    float* rowa = rowl + 64;

    const int qt   = blockIdx.x;
    const int h    = blockIdx.y;
    const int kvh  = h >> 2;
    const int tid  = threadIdx.x;
    const int lane = tid & 31;
    const int warp = tid >> 5;
    const int tx   = tid & 15, ty = tid >> 4;

    const float scale = 0.08838834764831845f;

    const float* qbase = g_qkv + (size_t)(qt * 64) * QKV_N + h * HD;
#pragma unroll
    for (int it = 0; it < 8; it++) {
        int r = warp + 8 * it;
        float4 q4 = *(const float4*)(qbase + (size_t)r * QKV_N + lane * 4);
        float* dst = Qs + r * KPAD + lane * 4;
        dst[0] = q4.x; dst[1] = q4.y; dst[2] = q4.z; dst[3] = q4.w;
    }
    if (tid < 64) { rowm[tid] = -INFINITY; rowl[tid] = 0.f; }

    float o[4][8];
#pragma unroll
    for (int i = 0; i < 4; i++)
#pragma unroll
        for (int j = 0; j < 8; j++) o[i][j] = 0.f;

    __syncthreads();

    for (int kt = 0; kt <= qt; kt++) {
        const float* kbase = g_qkv + (size_t)(kt * 64) * QKV_N + HID + kvh * HD;
        const float* vbase = kbase + NKV * HD;
#pragma unroll
        for (int it = 0; it < 8; it++) {
            int r = warp + 8 * it;
            float4 k4 = *(const float4*)(kbase + (size_t)r * QKV_N + lane * 4);
            float4 v4 = *(const float4*)(vbase + (size_t)r * QKV_N + lane * 4);
            float* kd = Ks + r * KPAD + lane * 4;
            kd[0] = k4.x; kd[1] = k4.y; kd[2] = k4.z; kd[3] = k4.w;
            float* vd = Vs + r * KPAD + lane * 4;
            vd[0] = v4.x; vd[1] = v4.y; vd[2] = v4.z; vd[3] = v4.w;
        }
        __syncthreads();

        float s[4][4];
#pragma unroll
        for (int i = 0; i < 4; i++)
#pragma unroll
            for (int j = 0; j < 4; j++) s[i][j] = 0.f;
#pragma unroll 8
        for (int d = 0; d < HD; d++) {
            float a[4], b[4];
#pragma unroll
            for (int i = 0; i < 4; i++) a[i] = Qs[(ty + 16 * i) * KPAD + d];
#pragma unroll
            for (int j = 0; j < 4; j++) b[j] = Ks[(tx + 16 * j) * KPAD + d];
#pragma unroll
            for (int i = 0; i < 4; i++)
#pragma unroll
                for (int j = 0; j < 4; j++) s[i][j] += a[i] * b[j];
        }
        const bool diag = (kt == qt);
#pragma unroll
        for (int i = 0; i < 4; i++) {
            const int qr = ty + 16 * i;
#pragma unroll
            for (int j = 0; j < 4; j++) {
                const int kc = tx + 16 * j;
                float sv = s[i][j] * scale;
                if (diag && kc > qr) sv = -INFINITY;
                Ss[qr * SSTR + kc] = sv;
            }
        }
        __syncthreads();

        {
            const int r = tid >> 2, part = tid & 3;
            float mloc = -INFINITY;
#pragma unroll
            for (int t = 0; t < 16; t++)
                mloc = fmaxf(mloc, Ss[r * SSTR + part * 16 + t]);
            mloc = fmaxf(mloc, __shfl_xor_sync(0xffffffffu, mloc, 1));
            mloc = fmaxf(mloc, __shfl_xor_sync(0xffffffffu, mloc, 2));
            const float mold = rowm[r];
            const float mnew = fmaxf(mold, mloc);
            float suml = 0.f;
#pragma unroll
            for (int t = 0; t < 16; t++) {
                const int idx = r * SSTR + part * 16 + t;
                float p = expf(Ss[idx] - mnew);
                Ss[idx] = p;
                suml += p;
            }
            suml += __shfl_xor_sync(0xffffffffu, suml, 1);
            suml += __shfl_xor_sync(0xffffffffu, suml, 2);
            if (part == 0) {
                const float alpha = expf(mold - mnew);
                rowa[r] = alpha;
                rowm[r] = mnew;
                rowl[r] = rowl[r] * alpha + suml;
            }
        }
        __syncthreads();

#pragma unroll
        for (int i = 0; i < 4; i++) {
            const float al = rowa[ty + 16 * i];
#pragma unroll
            for (int j = 0; j < 8; j++) o[i][j] *= al;
        }
#pragma unroll 8
        for (int c = 0; c < 64; c++) {
            float a[4], b[8];
#pragma unroll
            for (int i = 0; i < 4; i++) a[i] = Ss[(ty + 16 * i) * SSTR + c];
#pragma unroll
            for (int j = 0; j < 8; j++) b[j] = Vs[c * KPAD + tx + 16 * j];
#pragma unroll
            for (int i = 0; i < 4; i++)
#pragma unroll
                for (int j = 0; j < 8; j++) o[i][j] += a[i] * b[j];
        }
        __syncthreads();
    }

#pragma unroll
    for (int i = 0; i < 4; i++) {
        const int ry  = ty + 16 * i;
        const float inv = 1.0f / rowl[ry];
        const int m   = qt * 64 + ry;
#pragma unroll
        for (int j = 0; j < 8; j++)
            g_attn[(size_t)m * HID + h * HD + tx + 16 * j] = o[i][j] * inv;
    }
}

// ========================= launch ===========================================
extern "C" void kernel_launch(void* const* d_in, const int* in_sizes, int n_in,
                              void* d_out, int out_size)
{
    (void)in_sizes; (void)n_in; (void)out_size;
    const int*   positions = (const int*)  d_in[0];
    const float* X         = (const float*)d_in[1];
    const float* Wqkv      = (const float*)d_in[2];
    const float* bqkv      = (const float*)d_in[3];
    const float* Wproj     = (const float*)d_in[4];
    const float* bproj     = (const float*)d_in[5];
    float* out = (float*)d_out;

    float *qkv_p, *attn_p;
    cudaGetSymbolAddress((void**)&qkv_p,  g_qkv);
    cudaGetSymbolAddress((void**)&attn_p, g_attn);

    // 1) RoPE tables
    rope_table_kernel<<<(S_LEN * HALF + 255) / 256, 256>>>(positions);

    // 2) QKV GEMM (bias + RoPE over q,k columns)
    cudaFuncSetAttribute(hmma_gemm, cudaFuncAttributeMaxDynamicSharedMemorySize,
                         SMEM_GEMM);
    {
        dim3 grid(QKV_N / 128, S_LEN / 128);
        hmma_gemm<<<grid, 256, SMEM_GEMM>>>(X, Wqkv, bqkv, qkv_p, QKV_N, HID,
                                            HID + NKV * HD);
    }

    // 3) Flash attention (fp32)
    {
        const int smem = (3 * 64 * KPAD + 64 * SSTR + 3 * 64) * (int)sizeof(float);
        cudaFuncSetAttribute(flash_kernel,
                             cudaFuncAttributeMaxDynamicSharedMemorySize, smem);
        dim3 grid(S_LEN / 64, NH);
        flash_kernel<<<grid, 256, smem>>>();
    }

    // 4) Output projection
    {
        dim3 grid(HID / 128, S_LEN / 128);
        hmma_gemm<<<grid, 256, SMEM_GEMM>>>(attn_p, Wproj, bproj, out, HID, HID, 0);
    }
}

// round 5
// speedup vs baseline: 3.1618x; 1.3413x over previous
#include <cuda_runtime.h>
#include <cuda_bf16.h>
#include <math.h>
#include <stdint.h>

// ---------------------------------------------------------------------------
// CodeShellAttention round 5:
//   GEMMs: mma.sync bf16 hi/lo split (unchanged from R4, 54% tensor).
//   Flash attention: NEW — HMMA bf16 hi/lo split, FA2-style register P reuse.
// ---------------------------------------------------------------------------

#define S_LEN  2048
#define HID    4096
#define NH     32
#define NKV    8
#define HD     128
#define QKV_N  6144
#define HALF   64

__device__ float g_qkv[S_LEN * QKV_N];
__device__ float g_attn[S_LEN * HID];
__device__ float g_cos[S_LEN * HALF];
__device__ float g_sin[S_LEN * HALF];

// ========================= helpers =========================================
__device__ __forceinline__ uint32_t smem_u32(const void* p) {
    uint32_t a;
    asm("{ .reg .u64 t; cvta.to.shared.u64 t, %1; cvt.u32.u64 %0, t; }"
        : "=r"(a) : "l"(p));
    return a;
}

__device__ __forceinline__ void ldsm4(uint32_t* r, uint32_t addr) {
    asm volatile("ldmatrix.sync.aligned.m8n8.x4.shared.b16 {%0,%1,%2,%3}, [%4];"
                 : "=r"(r[0]), "=r"(r[1]), "=r"(r[2]), "=r"(r[3]) : "r"(addr));
}

__device__ __forceinline__ void ldsm4t(uint32_t* r, uint32_t addr) {
    asm volatile("ldmatrix.sync.aligned.m8n8.x4.trans.shared.b16 {%0,%1,%2,%3}, [%4];"
                 : "=r"(r[0]), "=r"(r[1]), "=r"(r[2]), "=r"(r[3]) : "r"(addr));
}

__device__ __forceinline__ void mma16816(float* d, const uint32_t* a,
                                         const uint32_t* b) {
    asm volatile(
        "mma.sync.aligned.m16n8k16.row.col.f32.bf16.bf16.f32 "
        "{%0,%1,%2,%3}, {%4,%5,%6,%7}, {%8,%9}, {%0,%1,%2,%3};"
        : "+f"(d[0]), "+f"(d[1]), "+f"(d[2]), "+f"(d[3])
        : "r"(a[0]), "r"(a[1]), "r"(a[2]), "r"(a[3]), "r"(b[0]), "r"(b[1]));
}

// truncation split of two floats into packed hi-bf16x2 / lo-bf16x2
__device__ __forceinline__ void split2(float x, float y, uint32_t& hi, uint32_t& lo)
{
    uint32_t bx = __float_as_uint(x), by = __float_as_uint(y);
    hi = __byte_perm(bx, by, 0x7632);
    float hx = __uint_as_float(bx & 0xFFFF0000u);
    float hy = __uint_as_float(by & 0xFFFF0000u);
    __nv_bfloat162 l = __floats2bfloat162_rn(x - hx, y - hy);
    lo = *reinterpret_cast<uint32_t*>(&l);
}

#define STS64(a, v0, v1) \
    asm volatile("st.shared.v2.u32 [%0], {%1, %2};" :: "r"(a), "r"(v0), "r"(v1) : "memory")
#define STS128(a, v0, v1, v2, v3) \
    asm volatile("st.shared.v4.u32 [%0], {%1, %2, %3, %4};" \
                 :: "r"(a), "r"(v0), "r"(v1), "r"(v2), "r"(v3) : "memory")

// ========================= RoPE tables =====================================
__global__ void rope_table_kernel(const int* __restrict__ positions)
{
    int i = blockIdx.x * blockDim.x + threadIdx.x;
    if (i >= S_LEN * HALF) return;
    int m = i >> 6;
    int d = i & 63;
    double p    = (double)positions[m];
    double invf = pow(10000.0, -((double)d) / 64.0);
    double a    = p * invf;
    g_cos[i] = (float)cos(a);
    g_sin[i] = (float)sin(a);
}

// ========================= HMMA GEMM (unchanged from R4) ====================
#define RSTR   144
#define TILEB  (128 * RSTR)
#define STAGEB (2 * TILEB)
#define SMEM_GEMM (2 * STAGEB)
#define ESTR   132

__global__ __launch_bounds__(256, 1)
void hmma_gemm(const float* __restrict__ A, const float* __restrict__ B,
               const float* __restrict__ bias, float* __restrict__ C,
               int N, int K, int rope_limit)
{
    extern __shared__ char smem[];
    const uint32_t sb = smem_u32(smem);

    const int tid  = threadIdx.x;
    const int lane = tid & 31;
    const int warp = tid >> 5;
    const int wm   = warp >> 2;
    const int wn   = warp & 3;
    const int bm   = blockIdx.y * 128;
    const int bn   = blockIdx.x * 128;

    const int arow = tid >> 3;
    const int acol = (tid & 7) * 4;
    const int bkg  = tid >> 6;
    const int bn2  = (tid & 63) * 2;

    const float* Aptr = A + (size_t)(bm + arow) * K + acol;
    const float* Bptr = B + (size_t)(bkg * 8) * N + bn + bn2;

    float acc[4][4][4];
#pragma unroll
    for (int i = 0; i < 4; i++)
#pragma unroll
        for (int j = 0; j < 4; j++)
#pragma unroll
            for (int t = 0; t < 4; t++) acc[i][j][t] = 0.f;

    const int nchunk = K >> 5;
    float4 areg[4];
    float2 breg[8];

#pragma unroll
    for (int i = 0; i < 4; i++)
        areg[i] = *(const float4*)(Aptr + (size_t)(32 * i) * K);
#pragma unroll
    for (int i = 0; i < 8; i++)
        breg[i] = *(const float2*)(Bptr + (size_t)i * N);

    auto sts_chunk = [&](int s) {
        const uint32_t stA = sb + s * STAGEB;
        const uint32_t stB = stA + TILEB;
#pragma unroll
        for (int i = 0; i < 4; i++) {
            uint32_t h01, l01, h23, l23;
            split2(areg[i].x, areg[i].y, h01, l01);
            split2(areg[i].z, areg[i].w, h23, l23);
            const uint32_t off = (uint32_t)((arow + 32 * i) * RSTR + acol * 2);
            STS64(stA + off,      h01, h23);
            STS64(stA + off + 64, l01, l23);
        }
        uint32_t hx[4], lx[4], hy[4], ly[4];
#pragma unroll
        for (int j = 0; j < 4; j++) {
            split2(breg[2 * j].x, breg[2 * j + 1].x, hx[j], lx[j]);
            split2(breg[2 * j].y, breg[2 * j + 1].y, hy[j], ly[j]);
        }
        const uint32_t o0 = (uint32_t)(bn2 * RSTR + bkg * 16);
        const uint32_t o1 = o0 + RSTR;
        STS128(stB + o0,      hx[0], hx[1], hx[2], hx[3]);
        STS128(stB + o0 + 64, lx[0], lx[1], lx[2], lx[3]);
        STS128(stB + o1,      hy[0], hy[1], hy[2], hy[3]);
        STS128(stB + o1 + 64, ly[0], ly[1], ly[2], ly[3]);
    };

    sts_chunk(0);
    __syncthreads();

    const uint32_t a_l = (uint32_t)((lane & 15) * RSTR + (lane >> 4) * 16);
    const uint32_t b_l = (uint32_t)(((lane & 7) + ((lane >> 4) & 1) * 8) * RSTR
                                    + ((lane >> 3) & 1) * 16);

    for (int c = 0; c < nchunk; c++) {
        const int s = c & 1;
        const uint32_t stA = sb + s * STAGEB;
        const uint32_t stB = stA + TILEB;

        if (c + 1 < nchunk) {
            const int k0 = (c + 1) << 5;
#pragma unroll
            for (int i = 0; i < 4; i++)
                areg[i] = *(const float4*)(Aptr + (size_t)(32 * i) * K + k0);
#pragma unroll
            for (int i = 0; i < 8; i++)
                breg[i] = *(const float2*)(Bptr + (size_t)(k0 + i) * N);
        }

#pragma unroll
        for (int ks = 0; ks < 2; ks++) {
            uint32_t ah[4][4], al[4][4], bh[4][2], bl[4][2];
#pragma unroll
            for (int mt = 0; mt < 4; mt++) {
                const uint32_t base = stA + a_l
                    + (uint32_t)((wm * 64 + mt * 16) * RSTR + ks * 32);
                ldsm4(ah[mt], base);
                ldsm4(al[mt], base + 64);
            }
#pragma unroll
            for (int np = 0; np < 2; np++) {
                const uint32_t base = stB + b_l
                    + (uint32_t)((wn * 32 + np * 16) * RSTR + ks * 32);
                uint32_t th[4], tl[4];
                ldsm4(th, base);
                ldsm4(tl, base + 64);
                bh[2 * np][0] = th[0]; bh[2 * np][1] = th[1];
                bh[2 * np + 1][0] = th[2]; bh[2 * np + 1][1] = th[3];
                bl[2 * np][0] = tl[0]; bl[2 * np][1] = tl[1];
                bl[2 * np + 1][0] = tl[2]; bl[2 * np + 1][1] = tl[3];
            }
#pragma unroll
            for (int mt = 0; mt < 4; mt++)
#pragma unroll
                for (int nt = 0; nt < 4; nt++) {
                    mma16816(acc[mt][nt], ah[mt], bh[nt]);
                    mma16816(acc[mt][nt], ah[mt], bl[nt]);
                    mma16816(acc[mt][nt], al[mt], bh[nt]);
                }
        }

        if (c + 1 < nchunk) {
            sts_chunk((c + 1) & 1);
            __syncthreads();
        }
    }

    __syncthreads();
    float* Ss = (float*)smem;
    {
        const int r0 = wm * 64 + (lane >> 2);
        const int c0 = wn * 32 + (lane & 3) * 2;
#pragma unroll
        for (int mt = 0; mt < 4; mt++)
#pragma unroll
            for (int nt = 0; nt < 4; nt++) {
                const int r = r0 + mt * 16;
                const int cc = c0 + nt * 8;
                *(float2*)&Ss[r * ESTR + cc] =
                    make_float2(acc[mt][nt][0], acc[mt][nt][1]);
                *(float2*)&Ss[(r + 8) * ESTR + cc] =
                    make_float2(acc[mt][nt][2], acc[mt][nt][3]);
            }
    }
    __syncthreads();

    {
        const int tx = tid & 15, ty = tid >> 4;
        const bool rope = (bn < rope_limit);
#pragma unroll
        for (int i = 0; i < 8; i++) {
            const int row = ty + 16 * i;
            const int m   = bm + row;
            float v[8];
#pragma unroll
            for (int j = 0; j < 8; j++)
                v[j] = Ss[row * ESTR + tx + 16 * j] + bias[bn + tx + 16 * j];
            if (rope) {
#pragma unroll
                for (int j = 0; j < 4; j++) {
                    const int d = tx + 16 * j;
                    const float cc = g_cos[m * HALF + d];
                    const float ssn = g_sin[m * HALF + d];
                    const float x1 = v[j], x2 = v[j + 4];
                    v[j]     = x1 * cc - x2 * ssn;
                    v[j + 4] = x2 * cc + x1 * ssn;
                }
            }
#pragma unroll
            for (int j = 0; j < 8; j++)
                C[(size_t)m * N + bn + tx + 16 * j] = v[j];
        }
    }
}

// ========================= Flash attention (HMMA) ===========================
// Br=128 (one head), Bc=64, 8 warps x 16 rows. Q frags in registers.
// Smem (64 KB): during prologue Qhi[0:32K) Qlo[32K:64K); in mainloop
// Khi[0:16K) Klo[16K:32K) Vhi[32K:48K) Vlo[48K:64K).
// Tiles: row stride 256B (128 bf16), 16B-granule XOR swizzle g^=(row&7).
#define FL_SMEM 65536

__global__ __launch_bounds__(256, 1)
void flash_hmma()
{
    extern __shared__ char smem[];
    const uint32_t sb = smem_u32(smem);
    const int tid  = threadIdx.x;
    const int lane = tid & 31;
    const int warp = tid >> 5;
    const int qt   = 15 - (int)blockIdx.x;   // heavy tiles first
    const int h    = blockIdx.y;
    const int kvh  = h >> 2;
    const int wr   = warp * 16;
    const float scale = 0.08838834764831845f;

    // ---- stage Q tile (128 x 128) hi/lo ----
    {
        const int r = tid >> 1;
        const int gbase = (tid & 1) * 8;
        const float* src = g_qkv + (size_t)(qt * 128 + r) * QKV_N + h * HD;
#pragma unroll
        for (int i = 0; i < 8; i++) {
            const int g = gbase + i;
            float4 v0 = *(const float4*)(src + g * 8);
            float4 v1 = *(const float4*)(src + g * 8 + 4);
            uint32_t h0, l0, h1, l1, h2, l2, h3, l3;
            split2(v0.x, v0.y, h0, l0);
            split2(v0.z, v0.w, h1, l1);
            split2(v1.x, v1.y, h2, l2);
            split2(v1.z, v1.w, h3, l3);
            const uint32_t off = (uint32_t)(r * 256 + ((g ^ (r & 7)) * 16));
            STS128(sb + off,         h0, h1, h2, h3);
            STS128(sb + 32768 + off, l0, l1, l2, l3);
        }
    }
    __syncthreads();

    // ---- Q fragments to registers: 8 k-steps x (hi,lo) ----
    uint32_t qh[8][4], ql[8][4];
    {
        const int r = wr + (lane & 15);
#pragma unroll
        for (int ks = 0; ks < 8; ks++) {
            const int g = ks * 2 + (lane >> 4);
            const uint32_t off = (uint32_t)(r * 256 + ((g ^ (r & 7)) * 16));
            ldsm4(qh[ks], sb + off);
            ldsm4(ql[ks], sb + 32768 + off);
        }
    }
    __syncthreads();

    float o[16][4];
#pragma unroll
    for (int f = 0; f < 16; f++)
#pragma unroll
        for (int e = 0; e < 4; e++) o[f][e] = 0.f;
    float m0 = -1e30f, m1 = -1e30f, l0 = 0.f, l1 = 0.f;

    const int row0 = qt * 128 + wr + (lane >> 2);
    const int ktmax = 2 * qt + 1;

    for (int kt = 0; kt <= ktmax; kt++) {
        // ---- load K/V tile (64 x 128) hi/lo ----
        {
            const int r = tid >> 2;
            const float* ksrc = g_qkv + (size_t)(kt * 64 + r) * QKV_N + HID + kvh * HD;
            const float* vsrc = ksrc + NKV * HD;
#pragma unroll
            for (int i = 0; i < 4; i++) {
                const int g = (tid & 3) * 4 + i;
                const uint32_t off = (uint32_t)(r * 256 + ((g ^ (r & 7)) * 16));
                float4 a0 = *(const float4*)(ksrc + g * 8);
                float4 a1 = *(const float4*)(ksrc + g * 8 + 4);
                uint32_t h0, l0r, h1, l1r, h2, l2r, h3, l3r;
                split2(a0.x, a0.y, h0, l0r);
                split2(a0.z, a0.w, h1, l1r);
                split2(a1.x, a1.y, h2, l2r);
                split2(a1.z, a1.w, h3, l3r);
                STS128(sb + off,         h0, h1, h2, h3);
                STS128(sb + 16384 + off, l0r, l1r, l2r, l3r);
                float4 b0 = *(const float4*)(vsrc + g * 8);
                float4 b1 = *(const float4*)(vsrc + g * 8 + 4);
                split2(b0.x, b0.y, h0, l0r);
                split2(b0.z, b0.w, h1, l1r);
                split2(b1.x, b1.y, h2, l2r);
                split2(b1.z, b1.w, h3, l3r);
                STS128(sb + 32768 + off, h0, h1, h2, h3);
                STS128(sb + 49152 + off, l0r, l1r, l2r, l3r);
            }
        }
        __syncthreads();

        // ---- S = Q K^T (16 x 64 per warp) ----
        float s[8][4];
#pragma unroll
        for (int f = 0; f < 8; f++)
#pragma unroll
            for (int e = 0; e < 4; e++) s[f][e] = 0.f;

#pragma unroll
        for (int ks = 0; ks < 8; ks++) {
#pragma unroll
            for (int kg = 0; kg < 4; kg++) {
                const int n = kg * 16 + (lane & 7) + ((lane >> 4) & 1) * 8;
                const int g = ks * 2 + ((lane >> 3) & 1);
                const uint32_t off = (uint32_t)(n * 256 + ((g ^ (n & 7)) * 16));
                uint32_t th[4], tl[4];
                ldsm4(th, sb + off);
                ldsm4(tl, sb + 16384 + off);
                uint32_t bh0[2] = {th[0], th[1]}, bh1[2] = {th[2], th[3]};
                uint32_t bl0[2] = {tl[0], tl[1]}, bl1[2] = {tl[2], tl[3]};
                mma16816(s[2 * kg],     qh[ks], bh0);
                mma16816(s[2 * kg],     qh[ks], bl0);
                mma16816(s[2 * kg],     ql[ks], bh0);
                mma16816(s[2 * kg + 1], qh[ks], bh1);
                mma16816(s[2 * kg + 1], qh[ks], bl1);
                mma16816(s[2 * kg + 1], ql[ks], bh1);
            }
        }

        // ---- scale + causal mask + online softmax ----
        const bool need_mask = (kt >= 2 * qt);
        float vmax0 = -1e30f, vmax1 = -1e30f;
#pragma unroll
        for (int f = 0; f < 8; f++) {
            const int colb = kt * 64 + f * 8 + 2 * (lane & 3);
#pragma unroll
            for (int e = 0; e < 2; e++) {
                float v = s[f][e] * scale;
                if (need_mask && (colb + e > row0)) v = -1e30f;
                s[f][e] = v;
                vmax0 = fmaxf(vmax0, v);
                float w = s[f][2 + e] * scale;
                if (need_mask && (colb + e > row0 + 8)) w = -1e30f;
                s[f][2 + e] = w;
                vmax1 = fmaxf(vmax1, w);
            }
        }
        vmax0 = fmaxf(vmax0, __shfl_xor_sync(0xffffffffu, vmax0, 1));
        vmax0 = fmaxf(vmax0, __shfl_xor_sync(0xffffffffu, vmax0, 2));
        vmax1 = fmaxf(vmax1, __shfl_xor_sync(0xffffffffu, vmax1, 1));
        vmax1 = fmaxf(vmax1, __shfl_xor_sync(0xffffffffu, vmax1, 2));

        const float mn0 = fmaxf(m0, vmax0);
        const float mn1 = fmaxf(m1, vmax1);
        const float al0 = __expf(m0 - mn0);
        const float al1 = __expf(m1 - mn1);
        m0 = mn0; m1 = mn1;

        float sum0 = 0.f, sum1 = 0.f;
#pragma unroll
        for (int f = 0; f < 8; f++) {
            s[f][0] = __expf(s[f][0] - mn0); sum0 += s[f][0];
            s[f][1] = __expf(s[f][1] - mn0); sum0 += s[f][1];
            s[f][2] = __expf(s[f][2] - mn1); sum1 += s[f][2];
            s[f][3] = __expf(s[f][3] - mn1); sum1 += s[f][3];
        }
        sum0 += __shfl_xor_sync(0xffffffffu, sum0, 1);
        sum0 += __shfl_xor_sync(0xffffffffu, sum0, 2);
        sum1 += __shfl_xor_sync(0xffffffffu, sum1, 1);
        sum1 += __shfl_xor_sync(0xffffffffu, sum1, 2);
        l0 = l0 * al0 + sum0;
        l1 = l1 * al1 + sum1;

#pragma unroll
        for (int f = 0; f < 16; f++) {
            o[f][0] *= al0; o[f][1] *= al0;
            o[f][2] *= al1; o[f][3] *= al1;
        }

        // ---- O += P V : P frags built from s regs (hi/lo) ----
#pragma unroll
        for (int ks = 0; ks < 4; ks++) {
            uint32_t ah[4], alo[4];
            split2(s[2 * ks][0],     s[2 * ks][1],     ah[0], alo[0]);
            split2(s[2 * ks][2],     s[2 * ks][3],     ah[1], alo[1]);
            split2(s[2 * ks + 1][0], s[2 * ks + 1][1], ah[2], alo[2]);
            split2(s[2 * ks + 1][2], s[2 * ks + 1][3], ah[3], alo[3]);
            const int r = ks * 16 + (lane & 15);
#pragma unroll
            for (int ng = 0; ng < 8; ng++) {
                const int g = ng * 2 + (lane >> 4);
                const uint32_t off = (uint32_t)(r * 256 + ((g ^ (r & 7)) * 16));
                uint32_t th[4], tl[4];
                ldsm4t(th, sb + 32768 + off);
                ldsm4t(tl, sb + 49152 + off);
                uint32_t bh0[2] = {th[0], th[1]}, bh1[2] = {th[2], th[3]};
                uint32_t bl0[2] = {tl[0], tl[1]}, bl1[2] = {tl[2], tl[3]};
                mma16816(o[2 * ng],     ah,  bh0);
                mma16816(o[2 * ng],     ah,  bl0);
                mma16816(o[2 * ng],     alo, bh0);
                mma16816(o[2 * ng + 1], ah,  bh1);
                mma16816(o[2 * ng + 1], ah,  bl1);
                mma16816(o[2 * ng + 1], alo, bh1);
            }
        }
        __syncthreads();
    }

    // ---- finalize ----
    const float inv0 = 1.f / l0;
    const float inv1 = 1.f / l1;
    float* dst = g_attn + (size_t)row0 * HID + h * HD + 2 * (lane & 3);
#pragma unroll
    for (int f = 0; f < 16; f++) {
        *(float2*)(dst + f * 8) = make_float2(o[f][0] * inv0, o[f][1] * inv0);
        *(float2*)(dst + (size_t)8 * HID + f * 8) =
            make_float2(o[f][2] * inv1, o[f][3] * inv1);
    }
}

// ========================= launch ===========================================
extern "C" void kernel_launch(void* const* d_in, const int* in_sizes, int n_in,
                              void* d_out, int out_size)
{
    (void)in_sizes; (void)n_in; (void)out_size;
    const int*   positions = (const int*)  d_in[0];
    const float* X         = (const float*)d_in[1];
    const float* Wqkv      = (const float*)d_in[2];
    const float* bqkv      = (const float*)d_in[3];
    const float* Wproj     = (const float*)d_in[4];
    const float* bproj     = (const float*)d_in[5];
    float* out = (float*)d_out;

    float *qkv_p, *attn_p;
    cudaGetSymbolAddress((void**)&qkv_p,  g_qkv);
    cudaGetSymbolAddress((void**)&attn_p, g_attn);

    // 1) RoPE tables
    rope_table_kernel<<<(S_LEN * HALF + 255) / 256, 256>>>(positions);

    // 2) QKV GEMM (bias + RoPE over q,k columns)
    cudaFuncSetAttribute(hmma_gemm, cudaFuncAttributeMaxDynamicSharedMemorySize,
                         SMEM_GEMM);
    {
        dim3 grid(QKV_N / 128, S_LEN / 128);
        hmma_gemm<<<grid, 256, SMEM_GEMM>>>(X, Wqkv, bqkv, qkv_p, QKV_N, HID,
                                            HID + NKV * HD);
    }

    // 3) Flash attention (HMMA)
    cudaFuncSetAttribute(flash_hmma, cudaFuncAttributeMaxDynamicSharedMemorySize,
                         FL_SMEM);
    {
        dim3 grid(S_LEN / 128, NH);
        flash_hmma<<<grid, 256, FL_SMEM>>>();
    }

    // 4) Output projection
    {
        dim3 grid(HID / 128, S_LEN / 128);
        hmma_gemm<<<grid, 256, SMEM_GEMM>>>(attn_p, Wproj, bproj, out, HID, HID, 0);
    }
}

// round 6
// speedup vs baseline: 3.2244x; 1.0198x over previous
#include <cuda_runtime.h>
#include <cuda_bf16.h>
#include <math.h>
#include <stdint.h>

// ---------------------------------------------------------------------------
// CodeShellAttention round 6:
//   Pre-split fp32 -> hi/lo bf16 for all GEMM operands (memory-bound passes),
//   then cp.async 4-stage pipelined HMMA GEMM (128x256, 512 thr, 16 warps).
//   Flash attention: unchanged R5 HMMA kernel.
// ---------------------------------------------------------------------------

#define S_LEN  2048
#define HID    4096
#define NH     32
#define NKV    8
#define HD     128
#define QKV_N  6144
#define HALF   64

__device__ float g_qkv[S_LEN * QKV_N];
__device__ float g_attn[S_LEN * HID];
__device__ float g_cos[S_LEN * HALF];
__device__ float g_sin[S_LEN * HALF];

__device__ __nv_bfloat16 g_Xhi[S_LEN * HID];
__device__ __nv_bfloat16 g_Xlo[S_LEN * HID];
__device__ __nv_bfloat16 g_Wq_hi[HID * QKV_N];
__device__ __nv_bfloat16 g_Wq_lo[HID * QKV_N];
__device__ __nv_bfloat16 g_Wp_hi[HID * HID];
__device__ __nv_bfloat16 g_Wp_lo[HID * HID];
__device__ __nv_bfloat16 g_Ahi[S_LEN * HID];
__device__ __nv_bfloat16 g_Alo[S_LEN * HID];

// ========================= helpers =========================================
__device__ __forceinline__ uint32_t smem_u32(const void* p) {
    uint32_t a;
    asm("{ .reg .u64 t; cvta.to.shared.u64 t, %1; cvt.u32.u64 %0, t; }"
        : "=r"(a) : "l"(p));
    return a;
}

__device__ __forceinline__ void ldsm4(uint32_t* r, uint32_t addr) {
    asm volatile("ldmatrix.sync.aligned.m8n8.x4.shared.b16 {%0,%1,%2,%3}, [%4];"
                 : "=r"(r[0]), "=r"(r[1]), "=r"(r[2]), "=r"(r[3]) : "r"(addr));
}

__device__ __forceinline__ void ldsm4t(uint32_t* r, uint32_t addr) {
    asm volatile("ldmatrix.sync.aligned.m8n8.x4.trans.shared.b16 {%0,%1,%2,%3}, [%4];"
                 : "=r"(r[0]), "=r"(r[1]), "=r"(r[2]), "=r"(r[3]) : "r"(addr));
}

__device__ __forceinline__ void mma16816(float* d, const uint32_t* a,
                                         const uint32_t* b) {
    asm volatile(
        "mma.sync.aligned.m16n8k16.row.col.f32.bf16.bf16.f32 "
        "{%0,%1,%2,%3}, {%4,%5,%6,%7}, {%8,%9}, {%0,%1,%2,%3};"
        : "+f"(d[0]), "+f"(d[1]), "+f"(d[2]), "+f"(d[3])
        : "r"(a[0]), "r"(a[1]), "r"(a[2]), "r"(a[3]), "r"(b[0]), "r"(b[1]));
}

__device__ __forceinline__ void split2(float x, float y, uint32_t& hi, uint32_t& lo)
{
    uint32_t bx = __float_as_uint(x), by = __float_as_uint(y);
    hi = __byte_perm(bx, by, 0x7632);
    float hx = __uint_as_float(bx & 0xFFFF0000u);
    float hy = __uint_as_float(by & 0xFFFF0000u);
    __nv_bfloat162 l = __floats2bfloat162_rn(x - hx, y - hy);
    lo = *reinterpret_cast<uint32_t*>(&l);
}

#define STS128(a, v0, v1, v2, v3) \
    asm volatile("st.shared.v4.u32 [%0], {%1, %2, %3, %4};" \
                 :: "r"(a), "r"(v0), "r"(v1), "r"(v2), "r"(v3) : "memory")

__device__ __forceinline__ void cp16(uint32_t saddr, const void* gaddr) {
    asm volatile("cp.async.cg.shared.global [%0], [%1], 16;"
                 :: "r"(saddr), "l"(gaddr) : "memory");
}
#define CP_COMMIT() asm volatile("cp.async.commit_group;" ::: "memory")
#define CP_WAIT2()  asm volatile("cp.async.wait_group 2;" ::: "memory")

// ========================= RoPE tables =====================================
__global__ void rope_table_kernel(const int* __restrict__ positions)
{
    int i = blockIdx.x * blockDim.x + threadIdx.x;
    if (i >= S_LEN * HALF) return;
    int m = i >> 6;
    int d = i & 63;
    double p    = (double)positions[m];
    double invf = pow(10000.0, -((double)d) / 64.0);
    double a    = p * invf;
    g_cos[i] = (float)cos(a);
    g_sin[i] = (float)sin(a);
}

// ========================= split pass ======================================
__global__ void split_kernel(const float4* __restrict__ in,
                             uint2* __restrict__ hi, uint2* __restrict__ lo,
                             int n4)
{
    int i = blockIdx.x * blockDim.x + threadIdx.x;
    if (i >= n4) return;
    float4 v = in[i];
    uint32_t h01, l01, h23, l23;
    split2(v.x, v.y, h01, l01);
    split2(v.z, v.w, h23, l23);
    hi[i] = make_uint2(h01, h23);
    lo[i] = make_uint2(l01, l23);
}

// ========================= cp.async HMMA GEMM ==============================
// C[M,N] = A @ B + bias (+RoPE). A,B pre-split hi/lo bf16. BM=128 BN=256
// BK=32, 512 threads (16 warps, 4x4 warp grid, warp tile 32x64), 4 stages.
#define G2_STG_A 8192
#define G2_STG_B 16384
#define G2_STG   49152
#define G2_SMEM  (4 * G2_STG)   // 196608
#define G2_ESTR  260

__global__ __launch_bounds__(512, 1)
void hmma_gemm2(const __nv_bfloat16* __restrict__ Ahi,
                const __nv_bfloat16* __restrict__ Alo,
                const __nv_bfloat16* __restrict__ Bhi,
                const __nv_bfloat16* __restrict__ Blo,
                const float* __restrict__ bias, float* __restrict__ C,
                int N, int K, int rope_limit)
{
    extern __shared__ char smem[];
    const uint32_t sb = smem_u32(smem);
    const int tid  = threadIdx.x;
    const int lane = tid & 31;
    const int warp = tid >> 5;
    const int wm   = warp >> 2;          // 0..3 (32 rows)
    const int wn   = warp & 3;           // 0..3 (64 cols)
    const int bm   = blockIdx.y * 128;
    const int bn   = blockIdx.x * 256;
    const int nchunk = K >> 5;

    // cp.async mapping (per stage): A: tid -> (m, cg); B: 2 chunks
    const int am = tid >> 2, acg = tid & 3;
    const uint32_t a_dst = (uint32_t)(am * 64 + ((acg ^ ((am >> 1) & 3)) << 4));
    const size_t a_src0 = (size_t)(bm + am) * K + acg * 8;

    const int bk0 = (tid * 2) >> 5, bg0 = (tid * 2) & 31;
    const int bk1 = (tid * 2 + 1) >> 5, bg1 = (tid * 2 + 1) & 31;
    const uint32_t b_dst0 = (uint32_t)(bk0 * 512 + ((bg0 ^ (bk0 & 7)) << 4));
    const uint32_t b_dst1 = (uint32_t)(bk1 * 512 + ((bg1 ^ (bk1 & 7)) << 4));

    auto issue = [&](int s, int c) {
        const uint32_t st = sb + s * G2_STG;
        const int k0 = c << 5;
        cp16(st + a_dst,            Ahi + a_src0 + k0);
        cp16(st + a_dst + G2_STG_A, Alo + a_src0 + k0);
        const size_t bs0 = (size_t)(k0 + bk0) * N + bn + bg0 * 8;
        const size_t bs1 = (size_t)(k0 + bk1) * N + bn + bg1 * 8;
        cp16(st + 16384 + b_dst0,            Bhi + bs0);
        cp16(st + 16384 + b_dst0 + G2_STG_B, Blo + bs0);
        cp16(st + 16384 + b_dst1,            Bhi + bs1);
        cp16(st + 16384 + b_dst1 + G2_STG_B, Blo + bs1);
    };

    float acc[2][8][4];
#pragma unroll
    for (int i = 0; i < 2; i++)
#pragma unroll
        for (int j = 0; j < 8; j++)
#pragma unroll
            for (int t = 0; t < 4; t++) acc[i][j][t] = 0.f;

    // prologue: 3 stages in flight
    issue(0, 0); CP_COMMIT();
    issue(1, 1); CP_COMMIT();
    issue(2, 2); CP_COMMIT();

    // per-lane ldsm constants
    const int a_row0 = wm * 32 + (lane & 15);
    const int b_g0   = wn * 8 + (lane >> 4);

    for (int c = 0; c < nchunk; c++) {
        CP_WAIT2();
        __syncthreads();
        if (c + 3 < nchunk) issue((c + 3) & 3, c + 3);
        CP_COMMIT();

        const uint32_t stA = sb + (c & 3) * G2_STG;
        const uint32_t stB = stA + 16384;

#pragma unroll
        for (int ks = 0; ks < 2; ks++) {
            uint32_t ah[2][4], al[2][4];
#pragma unroll
            for (int mt = 0; mt < 2; mt++) {
                const int row = a_row0 + mt * 16;
                const int cgl = ks * 2 + (lane >> 4);
                const uint32_t a = stA + (uint32_t)(row * 64
                                   + ((cgl ^ ((row >> 1) & 3)) << 4));
                ldsm4(ah[mt], a);
                ldsm4(al[mt], a + G2_STG_A);
            }
#pragma unroll
            for (int ng = 0; ng < 4; ng++) {
                const int r = ks * 16 + (lane & 15);
                const int g = b_g0 + ng * 2;
                const uint32_t b = stB + (uint32_t)(r * 512 + ((g ^ (r & 7)) << 4));
                uint32_t th[4], tl[4];
                ldsm4t(th, b);
                ldsm4t(tl, b + G2_STG_B);
                uint32_t bh0[2] = {th[0], th[1]}, bh1[2] = {th[2], th[3]};
                uint32_t bl0[2] = {tl[0], tl[1]}, bl1[2] = {tl[2], tl[3]};
#pragma unroll
                for (int mt = 0; mt < 2; mt++) {
                    mma16816(acc[mt][2 * ng],     ah[mt], bh0);
                    mma16816(acc[mt][2 * ng],     ah[mt], bl0);
                    mma16816(acc[mt][2 * ng],     al[mt], bh0);
                    mma16816(acc[mt][2 * ng + 1], ah[mt], bh1);
                    mma16816(acc[mt][2 * ng + 1], ah[mt], bl1);
                    mma16816(acc[mt][2 * ng + 1], al[mt], bh1);
                }
            }
        }
    }

    // ---- epilogue ----
    __syncthreads();
    float* Ss = (float*)smem;
    {
        const int r0 = wm * 32 + (lane >> 2);
        const int c0 = wn * 64 + (lane & 3) * 2;
#pragma unroll
        for (int mt = 0; mt < 2; mt++)
#pragma unroll
            for (int nt = 0; nt < 8; nt++) {
                const int r = r0 + mt * 16;
                const int cc = c0 + nt * 8;
                *(float2*)&Ss[r * G2_ESTR + cc] =
                    make_float2(acc[mt][nt][0], acc[mt][nt][1]);
                *(float2*)&Ss[(r + 8) * G2_ESTR + cc] =
                    make_float2(acc[mt][nt][2], acc[mt][nt][3]);
            }
    }
    __syncthreads();

    {
        const int tx = tid & 31, ty = tid >> 5;
        const bool rope = (bn < rope_limit);
#pragma unroll
        for (int i = 0; i < 8; i++) {
            const int row = ty + 16 * i;
            const int m   = bm + row;
            float v[8];
#pragma unroll
            for (int j = 0; j < 8; j++)
                v[j] = Ss[row * G2_ESTR + tx + 32 * j] + bias[bn + tx + 32 * j];
            if (rope) {
#pragma unroll
                for (int jj = 0; jj < 4; jj++) {
                    const int j = (jj & 1) + (jj >> 1) * 4;   // {0,1,4,5}
                    const int d = (tx + 32 * j) & 63;
                    const float cc  = g_cos[m * HALF + d];
                    const float ssn = g_sin[m * HALF + d];
                    const float x1 = v[j], x2 = v[j + 2];
                    v[j]     = x1 * cc - x2 * ssn;
                    v[j + 2] = x2 * cc + x1 * ssn;
                }
            }
#pragma unroll
            for (int j = 0; j < 8; j++)
                C[(size_t)m * N + bn + tx + 32 * j] = v[j];
        }
    }
}

// ========================= Flash attention (HMMA, R5) =======================
#define FL_SMEM 65536

__global__ __launch_bounds__(256, 1)
void flash_hmma()
{
    extern __shared__ char smem[];
    const uint32_t sb = smem_u32(smem);
    const int tid  = threadIdx.x;
    const int lane = tid & 31;
    const int warp = tid >> 5;
    const int qt   = 15 - (int)blockIdx.x;
    const int h    = blockIdx.y;
    const int kvh  = h >> 2;
    const int wr   = warp * 16;
    const float scale = 0.08838834764831845f;

    {
        const int r = tid >> 1;
        const int gbase = (tid & 1) * 8;
        const float* src = g_qkv + (size_t)(qt * 128 + r) * QKV_N + h * HD;
#pragma unroll
        for (int i = 0; i < 8; i++) {
            const int g = gbase + i;
            float4 v0 = *(const float4*)(src + g * 8);
            float4 v1 = *(const float4*)(src + g * 8 + 4);
            uint32_t h0, l0, h1, l1, h2, l2, h3, l3;
            split2(v0.x, v0.y, h0, l0);
            split2(v0.z, v0.w, h1, l1);
            split2(v1.x, v1.y, h2, l2);
            split2(v1.z, v1.w, h3, l3);
            const uint32_t off = (uint32_t)(r * 256 + ((g ^ (r & 7)) * 16));
            STS128(sb + off,         h0, h1, h2, h3);
            STS128(sb + 32768 + off, l0, l1, l2, l3);
        }
    }
    __syncthreads();

    uint32_t qh[8][4], ql[8][4];
    {
        const int r = wr + (lane & 15);
#pragma unroll
        for (int ks = 0; ks < 8; ks++) {
            const int g = ks * 2 + (lane >> 4);
            const uint32_t off = (uint32_t)(r * 256 + ((g ^ (r & 7)) * 16));
            ldsm4(qh[ks], sb + off);
            ldsm4(ql[ks], sb + 32768 + off);
        }
    }
    __syncthreads();

    float o[16][4];
#pragma unroll
    for (int f = 0; f < 16; f++)
#pragma unroll
        for (int e = 0; e < 4; e++) o[f][e] = 0.f;
    float m0 = -1e30f, m1 = -1e30f, l0 = 0.f, l1 = 0.f;

    const int row0 = qt * 128 + wr + (lane >> 2);
    const int ktmax = 2 * qt + 1;

    for (int kt = 0; kt <= ktmax; kt++) {
        {
            const int r = tid >> 2;
            const float* ksrc = g_qkv + (size_t)(kt * 64 + r) * QKV_N + HID + kvh * HD;
            const float* vsrc = ksrc + NKV * HD;
#pragma unroll
            for (int i = 0; i < 4; i++) {
                const int g = (tid & 3) * 4 + i;
                const uint32_t off = (uint32_t)(r * 256 + ((g ^ (r & 7)) * 16));
                float4 a0 = *(const float4*)(ksrc + g * 8);
                float4 a1 = *(const float4*)(ksrc + g * 8 + 4);
                uint32_t h0, l0r, h1, l1r, h2, l2r, h3, l3r;
                split2(a0.x, a0.y, h0, l0r);
                split2(a0.z, a0.w, h1, l1r);
                split2(a1.x, a1.y, h2, l2r);
                split2(a1.z, a1.w, h3, l3r);
                STS128(sb + off,         h0, h1, h2, h3);
                STS128(sb + 16384 + off, l0r, l1r, l2r, l3r);
                float4 b0 = *(const float4*)(vsrc + g * 8);
                float4 b1 = *(const float4*)(vsrc + g * 8 + 4);
                split2(b0.x, b0.y, h0, l0r);
                split2(b0.z, b0.w, h1, l1r);
                split2(b1.x, b1.y, h2, l2r);
                split2(b1.z, b1.w, h3, l3r);
                STS128(sb + 32768 + off, h0, h1, h2, h3);
                STS128(sb + 49152 + off, l0r, l1r, l2r, l3r);
            }
        }
        __syncthreads();

        float s[8][4];
#pragma unroll
        for (int f = 0; f < 8; f++)
#pragma unroll
            for (int e = 0; e < 4; e++) s[f][e] = 0.f;

#pragma unroll
        for (int ks = 0; ks < 8; ks++) {
#pragma unroll
            for (int kg = 0; kg < 4; kg++) {
                const int n = kg * 16 + (lane & 7) + ((lane >> 4) & 1) * 8;
                const int g = ks * 2 + ((lane >> 3) & 1);
                const uint32_t off = (uint32_t)(n * 256 + ((g ^ (n & 7)) * 16));
                uint32_t th[4], tl[4];
                ldsm4(th, sb + off);
                ldsm4(tl, sb + 16384 + off);
                uint32_t bh0[2] = {th[0], th[1]}, bh1[2] = {th[2], th[3]};
                uint32_t bl0[2] = {tl[0], tl[1]}, bl1[2] = {tl[2], tl[3]};
                mma16816(s[2 * kg],     qh[ks], bh0);
                mma16816(s[2 * kg],     qh[ks], bl0);
                mma16816(s[2 * kg],     ql[ks], bh0);
                mma16816(s[2 * kg + 1], qh[ks], bh1);
                mma16816(s[2 * kg + 1], qh[ks], bl1);
                mma16816(s[2 * kg + 1], ql[ks], bh1);
            }
        }

        const bool need_mask = (kt >= 2 * qt);
        float vmax0 = -1e30f, vmax1 = -1e30f;
#pragma unroll
        for (int f = 0; f < 8; f++) {
            const int colb = kt * 64 + f * 8 + 2 * (lane & 3);
#pragma unroll
            for (int e = 0; e < 2; e++) {
                float v = s[f][e] * scale;
                if (need_mask && (colb + e > row0)) v = -1e30f;
                s[f][e] = v;
                vmax0 = fmaxf(vmax0, v);
                float w = s[f][2 + e] * scale;
                if (need_mask && (colb + e > row0 + 8)) w = -1e30f;
                s[f][2 + e] = w;
                vmax1 = fmaxf(vmax1, w);
            }
        }
        vmax0 = fmaxf(vmax0, __shfl_xor_sync(0xffffffffu, vmax0, 1));
        vmax0 = fmaxf(vmax0, __shfl_xor_sync(0xffffffffu, vmax0, 2));
        vmax1 = fmaxf(vmax1, __shfl_xor_sync(0xffffffffu, vmax1, 1));
        vmax1 = fmaxf(vmax1, __shfl_xor_sync(0xffffffffu, vmax1, 2));

        const float mn0 = fmaxf(m0, vmax0);
        const float mn1 = fmaxf(m1, vmax1);
        const float al0 = __expf(m0 - mn0);
        const float al1 = __expf(m1 - mn1);
        m0 = mn0; m1 = mn1;

        float sum0 = 0.f, sum1 = 0.f;
#pragma unroll
        for (int f = 0; f < 8; f++) {
            s[f][0] = __expf(s[f][0] - mn0); sum0 += s[f][0];
            s[f][1] = __expf(s[f][1] - mn0); sum0 += s[f][1];
            s[f][2] = __expf(s[f][2] - mn1); sum1 += s[f][2];
            s[f][3] = __expf(s[f][3] - mn1); sum1 += s[f][3];
        }
        sum0 += __shfl_xor_sync(0xffffffffu, sum0, 1);
        sum0 += __shfl_xor_sync(0xffffffffu, sum0, 2);
        sum1 += __shfl_xor_sync(0xffffffffu, sum1, 1);
        sum1 += __shfl_xor_sync(0xffffffffu, sum1, 2);
        l0 = l0 * al0 + sum0;
        l1 = l1 * al1 + sum1;

#pragma unroll
        for (int f = 0; f < 16; f++) {
            o[f][0] *= al0; o[f][1] *= al0;
            o[f][2] *= al1; o[f][3] *= al1;
        }

#pragma unroll
        for (int ks = 0; ks < 4; ks++) {
            uint32_t ah[4], alo[4];
            split2(s[2 * ks][0],     s[2 * ks][1],     ah[0], alo[0]);
            split2(s[2 * ks][2],     s[2 * ks][3],     ah[1], alo[1]);
            split2(s[2 * ks + 1][0], s[2 * ks + 1][1], ah[2], alo[2]);
            split2(s[2 * ks + 1][2], s[2 * ks + 1][3], ah[3], alo[3]);
            const int r = ks * 16 + (lane & 15);
#pragma unroll
            for (int ng = 0; ng < 8; ng++) {
                const int g = ng * 2 + (lane >> 4);
                const uint32_t off = (uint32_t)(r * 256 + ((g ^ (r & 7)) * 16));
                uint32_t th[4], tl[4];
                ldsm4t(th, sb + 32768 + off);
                ldsm4t(tl, sb + 49152 + off);
                uint32_t bh0[2] = {th[0], th[1]}, bh1[2] = {th[2], th[3]};
                uint32_t bl0[2] = {tl[0], tl[1]}, bl1[2] = {tl[2], tl[3]};
                mma16816(o[2 * ng],     ah,  bh0);
                mma16816(o[2 * ng],     ah,  bl0);
                mma16816(o[2 * ng],     alo, bh0);
                mma16816(o[2 * ng + 1], ah,  bh1);
                mma16816(o[2 * ng + 1], ah,  bl1);
                mma16816(o[2 * ng + 1], alo, bh1);
            }
        }
        __syncthreads();
    }

    const float inv0 = 1.f / l0;
    const float inv1 = 1.f / l1;
    float* dst = g_attn + (size_t)row0 * HID + h * HD + 2 * (lane & 3);
#pragma unroll
    for (int f = 0; f < 16; f++) {
        *(float2*)(dst + f * 8) = make_float2(o[f][0] * inv0, o[f][1] * inv0);
        *(float2*)(dst + (size_t)8 * HID + f * 8) =
            make_float2(o[f][2] * inv1, o[f][3] * inv1);
    }
}

// ========================= launch ===========================================
extern "C" void kernel_launch(void* const* d_in, const int* in_sizes, int n_in,
                              void* d_out, int out_size)
{
    (void)in_sizes; (void)n_in; (void)out_size;
    const int*   positions = (const int*)  d_in[0];
    const float* X         = (const float*)d_in[1];
    const float* Wqkv      = (const float*)d_in[2];
    const float* bqkv      = (const float*)d_in[3];
    const float* Wproj     = (const float*)d_in[4];
    const float* bproj     = (const float*)d_in[5];
    float* out = (float*)d_out;

    float *qkv_p, *attn_p;
    cudaGetSymbolAddress((void**)&qkv_p,  g_qkv);
    cudaGetSymbolAddress((void**)&attn_p, g_attn);
    __nv_bfloat16 *xhi, *xlo, *wqhi, *wqlo, *wphi, *wplo, *ahi, *alo;
    cudaGetSymbolAddress((void**)&xhi,  g_Xhi);
    cudaGetSymbolAddress((void**)&xlo,  g_Xlo);
    cudaGetSymbolAddress((void**)&wqhi, g_Wq_hi);
    cudaGetSymbolAddress((void**)&wqlo, g_Wq_lo);
    cudaGetSymbolAddress((void**)&wphi, g_Wp_hi);
    cudaGetSymbolAddress((void**)&wplo, g_Wp_lo);
    cudaGetSymbolAddress((void**)&ahi,  g_Ahi);
    cudaGetSymbolAddress((void**)&alo,  g_Alo);

    // 1) RoPE tables
    rope_table_kernel<<<(S_LEN * HALF + 255) / 256, 256>>>(positions);

    // 2) split passes
    {
        int n4 = S_LEN * HID / 4;
        split_kernel<<<(n4 + 255) / 256, 256>>>((const float4*)X,
                                                (uint2*)xhi, (uint2*)xlo, n4);
    }
    {
        int n4 = HID * QKV_N / 4;
        split_kernel<<<(n4 + 255) / 256, 256>>>((const float4*)Wqkv,
                                                (uint2*)wqhi, (uint2*)wqlo, n4);
    }
    {
        int n4 = HID * HID / 4;
        split_kernel<<<(n4 + 255) / 256, 256>>>((const float4*)Wproj,
                                                (uint2*)wphi, (uint2*)wplo, n4);
    }

    // 3) QKV GEMM
    cudaFuncSetAttribute(hmma_gemm2, cudaFuncAttributeMaxDynamicSharedMemorySize,
                         G2_SMEM);
    {
        dim3 grid(QKV_N / 256, S_LEN / 128);
        hmma_gemm2<<<grid, 512, G2_SMEM>>>(xhi, xlo, wqhi, wqlo, bqkv, qkv_p,
                                           QKV_N, HID, HID + NKV * HD);
    }

    // 4) Flash attention
    cudaFuncSetAttribute(flash_hmma, cudaFuncAttributeMaxDynamicSharedMemorySize,
                         FL_SMEM);
    {
        dim3 grid(S_LEN / 128, NH);
        flash_hmma<<<grid, 256, FL_SMEM>>>();
    }

    // 5) split attn, then output projection
    {
        int n4 = S_LEN * HID / 4;
        split_kernel<<<(n4 + 255) / 256, 256>>>((const float4*)attn_p,
                                                (uint2*)ahi, (uint2*)alo, n4);
    }
    {
        dim3 grid(HID / 256, S_LEN / 128);
        hmma_gemm2<<<grid, 512, G2_SMEM>>>(ahi, alo, wphi, wplo, bproj, out,
                                           HID, HID, 0);
    }
}

// round 7
// speedup vs baseline: 3.6311x; 1.1262x over previous
#include <cuda_runtime.h>
#include <cuda_bf16.h>
#include <math.h>
#include <stdint.h>

// ---------------------------------------------------------------------------
// CodeShellAttention round 7:
//   - QKV GEMM epilogue writes pre-split bf16 hi/lo Q/K/V (no fp32 qkv).
//   - Flash: cp.async 2-stage K/V pipeline on pre-split operands; finalize
//     writes pre-split attn for the proj GEMM.
//   - GEMM mainloop unchanged from R6 (cp.async 4-stage HMMA).
// ---------------------------------------------------------------------------

#define S_LEN  2048
#define HID    4096
#define NH     32
#define NKV    8
#define HD     128
#define QKV_N  6144
#define KV_DIM 1024
#define HALF   64

__device__ float g_cos[S_LEN * HALF];
__device__ float g_sin[S_LEN * HALF];

__device__ __nv_bfloat16 g_Xhi[S_LEN * HID];
__device__ __nv_bfloat16 g_Xlo[S_LEN * HID];
__device__ __nv_bfloat16 g_Wq_hi[HID * QKV_N];
__device__ __nv_bfloat16 g_Wq_lo[HID * QKV_N];
__device__ __nv_bfloat16 g_Wp_hi[HID * HID];
__device__ __nv_bfloat16 g_Wp_lo[HID * HID];

__device__ __nv_bfloat16 g_Qhi[S_LEN * HID];
__device__ __nv_bfloat16 g_Qlo[S_LEN * HID];
__device__ __nv_bfloat16 g_Khi[S_LEN * KV_DIM];
__device__ __nv_bfloat16 g_Klo[S_LEN * KV_DIM];
__device__ __nv_bfloat16 g_Vhi[S_LEN * KV_DIM];
__device__ __nv_bfloat16 g_Vlo[S_LEN * KV_DIM];
__device__ __nv_bfloat16 g_Ahi[S_LEN * HID];
__device__ __nv_bfloat16 g_Alo[S_LEN * HID];

// ========================= helpers =========================================
__device__ __forceinline__ uint32_t smem_u32(const void* p) {
    uint32_t a;
    asm("{ .reg .u64 t; cvta.to.shared.u64 t, %1; cvt.u32.u64 %0, t; }"
        : "=r"(a) : "l"(p));
    return a;
}

__device__ __forceinline__ void ldsm4(uint32_t* r, uint32_t addr) {
    asm volatile("ldmatrix.sync.aligned.m8n8.x4.shared.b16 {%0,%1,%2,%3}, [%4];"
                 : "=r"(r[0]), "=r"(r[1]), "=r"(r[2]), "=r"(r[3]) : "r"(addr));
}

__device__ __forceinline__ void ldsm4t(uint32_t* r, uint32_t addr) {
    asm volatile("ldmatrix.sync.aligned.m8n8.x4.trans.shared.b16 {%0,%1,%2,%3}, [%4];"
                 : "=r"(r[0]), "=r"(r[1]), "=r"(r[2]), "=r"(r[3]) : "r"(addr));
}

__device__ __forceinline__ void mma16816(float* d, const uint32_t* a,
                                         const uint32_t* b) {
    asm volatile(
        "mma.sync.aligned.m16n8k16.row.col.f32.bf16.bf16.f32 "
        "{%0,%1,%2,%3}, {%4,%5,%6,%7}, {%8,%9}, {%0,%1,%2,%3};"
        : "+f"(d[0]), "+f"(d[1]), "+f"(d[2]), "+f"(d[3])
        : "r"(a[0]), "r"(a[1]), "r"(a[2]), "r"(a[3]), "r"(b[0]), "r"(b[1]));
}

__device__ __forceinline__ void split2(float x, float y, uint32_t& hi, uint32_t& lo)
{
    uint32_t bx = __float_as_uint(x), by = __float_as_uint(y);
    hi = __byte_perm(bx, by, 0x7632);
    float hx = __uint_as_float(bx & 0xFFFF0000u);
    float hy = __uint_as_float(by & 0xFFFF0000u);
    __nv_bfloat162 l = __floats2bfloat162_rn(x - hx, y - hy);
    lo = *reinterpret_cast<uint32_t*>(&l);
}

__device__ __forceinline__ void cp16(uint32_t saddr, const void* gaddr) {
    asm volatile("cp.async.cg.shared.global [%0], [%1], 16;"
                 :: "r"(saddr), "l"(gaddr) : "memory");
}
#define CP_COMMIT() asm volatile("cp.async.commit_group;" ::: "memory")
#define CP_WAIT0()  asm volatile("cp.async.wait_group 0;" ::: "memory")
#define CP_WAIT1()  asm volatile("cp.async.wait_group 1;" ::: "memory")
#define CP_WAIT2()  asm volatile("cp.async.wait_group 2;" ::: "memory")

// ========================= RoPE tables =====================================
__global__ void rope_table_kernel(const int* __restrict__ positions)
{
    int i = blockIdx.x * blockDim.x + threadIdx.x;
    if (i >= S_LEN * HALF) return;
    int m = i >> 6;
    int d = i & 63;
    double p    = (double)positions[m];
    double invf = pow(10000.0, -((double)d) / 64.0);
    double a    = p * invf;
    g_cos[i] = (float)cos(a);
    g_sin[i] = (float)sin(a);
}

// ========================= split pass ======================================
__global__ void split_kernel(const float4* __restrict__ in,
                             uint2* __restrict__ hi, uint2* __restrict__ lo,
                             int n4)
{
    int i = blockIdx.x * blockDim.x + threadIdx.x;
    if (i >= n4) return;
    float4 v = in[i];
    uint32_t h01, l01, h23, l23;
    split2(v.x, v.y, h01, l01);
    split2(v.z, v.w, h23, l23);
    hi[i] = make_uint2(h01, h23);
    lo[i] = make_uint2(l01, l23);
}

// ========================= cp.async HMMA GEMM ==============================
// BM=128 BN=256 BK=32, 512 threads, 4 stages.
// mode 0: C = acc + bias (fp32 out, proj)
// mode 1: QKV — bias + RoPE(q,k), split hi/lo bf16 into g_Q/K/V arrays.
#define G2_STG_A 8192
#define G2_STG_B 16384
#define G2_STG   49152
#define G2_SMEM  (4 * G2_STG)
#define G2_ESTR  260

__global__ __launch_bounds__(512, 1)
void hmma_gemm2(const __nv_bfloat16* __restrict__ Ahi,
                const __nv_bfloat16* __restrict__ Alo,
                const __nv_bfloat16* __restrict__ Bhi,
                const __nv_bfloat16* __restrict__ Blo,
                const float* __restrict__ bias, float* __restrict__ C,
                int N, int K, int mode)
{
    extern __shared__ char smem[];
    const uint32_t sb = smem_u32(smem);
    const int tid  = threadIdx.x;
    const int lane = tid & 31;
    const int warp = tid >> 5;
    const int wm   = warp >> 2;
    const int wn   = warp & 3;
    const int bm   = blockIdx.y * 128;
    const int bn   = blockIdx.x * 256;
    const int nchunk = K >> 5;

    const int am = tid >> 2, acg = tid & 3;
    const uint32_t a_dst = (uint32_t)(am * 64 + ((acg ^ ((am >> 1) & 3)) << 4));
    const size_t a_src0 = (size_t)(bm + am) * K + acg * 8;

    const int bk0 = (tid * 2) >> 5, bg0 = (tid * 2) & 31;
    const int bk1 = (tid * 2 + 1) >> 5, bg1 = (tid * 2 + 1) & 31;
    const uint32_t b_dst0 = (uint32_t)(bk0 * 512 + ((bg0 ^ (bk0 & 7)) << 4));
    const uint32_t b_dst1 = (uint32_t)(bk1 * 512 + ((bg1 ^ (bk1 & 7)) << 4));

    auto issue = [&](int s, int c) {
        const uint32_t st = sb + s * G2_STG;
        const int k0 = c << 5;
        cp16(st + a_dst,            Ahi + a_src0 + k0);
        cp16(st + a_dst + G2_STG_A, Alo + a_src0 + k0);
        const size_t bs0 = (size_t)(k0 + bk0) * N + bn + bg0 * 8;
        const size_t bs1 = (size_t)(k0 + bk1) * N + bn + bg1 * 8;
        cp16(st + 16384 + b_dst0,            Bhi + bs0);
        cp16(st + 16384 + b_dst0 + G2_STG_B, Blo + bs0);
        cp16(st + 16384 + b_dst1,            Bhi + bs1);
        cp16(st + 16384 + b_dst1 + G2_STG_B, Blo + bs1);
    };

    float acc[2][8][4];
#pragma unroll
    for (int i = 0; i < 2; i++)
#pragma unroll
        for (int j = 0; j < 8; j++)
#pragma unroll
            for (int t = 0; t < 4; t++) acc[i][j][t] = 0.f;

    issue(0, 0); CP_COMMIT();
    issue(1, 1); CP_COMMIT();
    issue(2, 2); CP_COMMIT();

    const int a_row0 = wm * 32 + (lane & 15);
    const int b_g0   = wn * 8 + (lane >> 4);

    for (int c = 0; c < nchunk; c++) {
        CP_WAIT2();
        __syncthreads();
        if (c + 3 < nchunk) issue((c + 3) & 3, c + 3);
        CP_COMMIT();

        const uint32_t stA = sb + (c & 3) * G2_STG;
        const uint32_t stB = stA + 16384;

#pragma unroll
        for (int ks = 0; ks < 2; ks++) {
            uint32_t ah[2][4], al[2][4];
#pragma unroll
            for (int mt = 0; mt < 2; mt++) {
                const int row = a_row0 + mt * 16;
                const int cgl = ks * 2 + (lane >> 4);
                const uint32_t a = stA + (uint32_t)(row * 64
                                   + ((cgl ^ ((row >> 1) & 3)) << 4));
                ldsm4(ah[mt], a);
                ldsm4(al[mt], a + G2_STG_A);
            }
#pragma unroll
            for (int ng = 0; ng < 4; ng++) {
                const int r = ks * 16 + (lane & 15);
                const int g = b_g0 + ng * 2;
                const uint32_t b = stB + (uint32_t)(r * 512 + ((g ^ (r & 7)) << 4));
                uint32_t th[4], tl[4];
                ldsm4t(th, b);
                ldsm4t(tl, b + G2_STG_B);
                uint32_t bh0[2] = {th[0], th[1]}, bh1[2] = {th[2], th[3]};
                uint32_t bl0[2] = {tl[0], tl[1]}, bl1[2] = {tl[2], tl[3]};
#pragma unroll
                for (int mt = 0; mt < 2; mt++) {
                    mma16816(acc[mt][2 * ng],     ah[mt], bh0);
                    mma16816(acc[mt][2 * ng],     ah[mt], bl0);
                    mma16816(acc[mt][2 * ng],     al[mt], bh0);
                    mma16816(acc[mt][2 * ng + 1], ah[mt], bh1);
                    mma16816(acc[mt][2 * ng + 1], ah[mt], bl1);
                    mma16816(acc[mt][2 * ng + 1], al[mt], bh1);
                }
            }
        }
    }

    // ---- stage accumulators to smem fp32 ----
    __syncthreads();
    float* Ss = (float*)smem;
    {
        const int r0 = wm * 32 + (lane >> 2);
        const int c0 = wn * 64 + (lane & 3) * 2;
#pragma unroll
        for (int mt = 0; mt < 2; mt++)
#pragma unroll
            for (int nt = 0; nt < 8; nt++) {
                const int r = r0 + mt * 16;
                const int cc = c0 + nt * 8;
                *(float2*)&Ss[r * G2_ESTR + cc] =
                    make_float2(acc[mt][nt][0], acc[mt][nt][1]);
                *(float2*)&Ss[(r + 8) * G2_ESTR + cc] =
                    make_float2(acc[mt][nt][2], acc[mt][nt][3]);
            }
    }
    __syncthreads();

    if (mode == 0) {
        const int tx = tid & 31, ty = tid >> 5;
#pragma unroll
        for (int i = 0; i < 8; i++) {
            const int row = ty + 16 * i;
            const int m   = bm + row;
            float v[8];
#pragma unroll
            for (int j = 0; j < 8; j++)
                v[j] = Ss[row * G2_ESTR + tx + 32 * j] + bias[bn + tx + 32 * j];
#pragma unroll
            for (int j = 0; j < 8; j++)
                C[(size_t)m * N + bn + tx + 32 * j] = v[j];
        }
    } else {
        // QKV epilogue: bias + RoPE(q,k) + hi/lo split to g_Q/K/V
        uint32_t* Qh = (uint32_t*)g_Qhi;  uint32_t* Ql = (uint32_t*)g_Qlo;
        uint32_t* Kh = (uint32_t*)g_Khi;  uint32_t* Kl = (uint32_t*)g_Klo;
        uint32_t* Vh = (uint32_t*)g_Vhi;  uint32_t* Vl = (uint32_t*)g_Vlo;
        const int tx = tid & 15, ty = tid >> 4;
        const bool rope = (bn < HID + KV_DIM);
#pragma unroll
        for (int i = 0; i < 4; i++) {
            const int row = ty + 32 * i;
            const int m   = bm + row;
            float2 p[8];
#pragma unroll
            for (int j = 0; j < 8; j++) {
                p[j] = *(const float2*)&Ss[row * G2_ESTR + 2 * tx + 32 * j];
                float2 bb = *(const float2*)&bias[bn + 2 * tx + 32 * j];
                p[j].x += bb.x;
                p[j].y += bb.y;
            }
            if (rope) {
#pragma unroll
                for (int jj = 0; jj < 4; jj++) {
                    const int j = (jj & 1) + (jj >> 1) * 4;  // {0,1,4,5}
                    const int d0 = (2 * tx + 32 * j) & 63;
                    const float c0 = g_cos[m * HALF + d0];
                    const float s0 = g_sin[m * HALF + d0];
                    const float c1 = g_cos[m * HALF + d0 + 1];
                    const float s1 = g_sin[m * HALF + d0 + 1];
                    float x1 = p[j].x, x2 = p[j + 2].x;
                    p[j].x     = x1 * c0 - x2 * s0;
                    p[j + 2].x = x2 * c0 + x1 * s0;
                    x1 = p[j].y; x2 = p[j + 2].y;
                    p[j].y     = x1 * c1 - x2 * s1;
                    p[j + 2].y = x2 * c1 + x1 * s1;
                }
            }
#pragma unroll
            for (int j = 0; j < 8; j++) {
                uint32_t hi, lo;
                split2(p[j].x, p[j].y, hi, lo);
                const int col = bn + 2 * tx + 32 * j;
                if (col < HID) {
                    const int idx = (m * HID + col) >> 1;
                    Qh[idx] = hi; Ql[idx] = lo;
                } else if (col < HID + KV_DIM) {
                    const int idx = (m * KV_DIM + col - HID) >> 1;
                    Kh[idx] = hi; Kl[idx] = lo;
                } else {
                    const int idx = (m * KV_DIM + col - HID - KV_DIM) >> 1;
                    Vh[idx] = hi; Vl[idx] = lo;
                }
            }
        }
    }
}

// ========================= Flash attention (cp.async HMMA) ==================
// Br=128 (one head), Bc=64, 8 warps. Pre-split Q/K/V from global.
// Smem: 2 stages x 64KB: Khi[0,16K) Klo[16K,32K) Vhi[32K,48K) Vlo[48K,64K).
// Q staged at [0,64K) during prologue only.
#define FL_SMEM 131072

__global__ __launch_bounds__(256, 1)
void flash_hmma()
{
    extern __shared__ char smem[];
    const uint32_t sb = smem_u32(smem);
    const int tid  = threadIdx.x;
    const int lane = tid & 31;
    const int warp = tid >> 5;
    const int qt   = 15 - (int)blockIdx.x;   // heavy tiles first
    const int h    = blockIdx.y;
    const int kvh  = h >> 2;
    const int wr   = warp * 16;
    const float scale = 0.08838834764831845f;

    const char* pQh = (const char*)g_Qhi;
    const char* pQl = (const char*)g_Qlo;
    const char* pKh = (const char*)g_Khi;
    const char* pKl = (const char*)g_Klo;
    const char* pVh = (const char*)g_Vhi;
    const char* pVl = (const char*)g_Vlo;

    // ---- prologue: stage Q (cp.async), extract fragments ----
    {
        const int r = tid >> 1;
        const int gb = (tid & 1) * 8;
#pragma unroll
        for (int i = 0; i < 8; i++) {
            const int g = gb + i;
            const size_t src = ((size_t)(qt * 128 + r) * HID + h * HD + g * 8) * 2;
            const uint32_t off = (uint32_t)(r * 256 + ((g ^ (r & 7)) << 4));
            cp16(sb + off,         pQh + src);
            cp16(sb + 32768 + off, pQl + src);
        }
    }
    CP_COMMIT();
    CP_WAIT0();
    __syncthreads();

    uint32_t qh[8][4], ql[8][4];
    {
        const int r = wr + (lane & 15);
#pragma unroll
        for (int ks = 0; ks < 8; ks++) {
            const int g = ks * 2 + (lane >> 4);
            const uint32_t off = (uint32_t)(r * 256 + ((g ^ (r & 7)) << 4));
            ldsm4(qh[ks], sb + off);
            ldsm4(ql[ks], sb + 32768 + off);
        }
    }
    __syncthreads();

    // K/V stage loader: 64 rows x 16 granules, 4 arrays
    const int lr = tid >> 2;
    const int lgb = (tid & 3) * 4;
    auto issue = [&](int kt, int s) {
        const uint32_t base = sb + s * 65536;
#pragma unroll
        for (int i = 0; i < 4; i++) {
            const int g = lgb + i;
            const size_t src =
                ((size_t)(kt * 64 + lr) * KV_DIM + kvh * HD + g * 8) * 2;
            const uint32_t off = (uint32_t)(lr * 256 + ((g ^ (lr & 7)) << 4));
            cp16(base + off,         pKh + src);
            cp16(base + 16384 + off, pKl + src);
            cp16(base + 32768 + off, pVh + src);
            cp16(base + 49152 + off, pVl + src);
        }
    };

    const int ktmax = 2 * qt + 1;
    issue(0, 0); CP_COMMIT();
    issue(1, 1); CP_COMMIT();

    float o[16][4];
#pragma unroll
    for (int f = 0; f < 16; f++)
#pragma unroll
        for (int e = 0; e < 4; e++) o[f][e] = 0.f;
    float m0 = -1e30f, m1 = -1e30f, l0 = 0.f, l1 = 0.f;

    const int row0 = qt * 128 + wr + (lane >> 2);

    for (int kt = 0; kt <= ktmax; kt++) {
        CP_WAIT1();
        __syncthreads();
        const uint32_t base = sb + (kt & 1) * 65536;

        // ---- S = Q K^T ----
        float s[8][4];
#pragma unroll
        for (int f = 0; f < 8; f++)
#pragma unroll
            for (int e = 0; e < 4; e++) s[f][e] = 0.f;

#pragma unroll
        for (int ks = 0; ks < 8; ks++) {
#pragma unroll
            for (int kg = 0; kg < 4; kg++) {
                const int n = kg * 16 + (lane & 7) + ((lane >> 4) & 1) * 8;
                const int g = ks * 2 + ((lane >> 3) & 1);
                const uint32_t off = base + (uint32_t)(n * 256 + ((g ^ (n & 7)) << 4));
                uint32_t th[4], tl[4];
                ldsm4(th, off);
                ldsm4(tl, off + 16384);
                uint32_t bh0[2] = {th[0], th[1]}, bh1[2] = {th[2], th[3]};
                uint32_t bl0[2] = {tl[0], tl[1]}, bl1[2] = {tl[2], tl[3]};
                mma16816(s[2 * kg],     qh[ks], bh0);
                mma16816(s[2 * kg],     qh[ks], bl0);
                mma16816(s[2 * kg],     ql[ks], bh0);
                mma16816(s[2 * kg + 1], qh[ks], bh1);
                mma16816(s[2 * kg + 1], qh[ks], bl1);
                mma16816(s[2 * kg + 1], ql[ks], bh1);
            }
        }

        // ---- softmax ----
        const bool need_mask = (kt >= 2 * qt);
        float vmax0 = -1e30f, vmax1 = -1e30f;
#pragma unroll
        for (int f = 0; f < 8; f++) {
            const int colb = kt * 64 + f * 8 + 2 * (lane & 3);
#pragma unroll
            for (int e = 0; e < 2; e++) {
                float v = s[f][e] * scale;
                if (need_mask && (colb + e > row0)) v = -1e30f;
                s[f][e] = v;
                vmax0 = fmaxf(vmax0, v);
                float w = s[f][2 + e] * scale;
                if (need_mask && (colb + e > row0 + 8)) w = -1e30f;
                s[f][2 + e] = w;
                vmax1 = fmaxf(vmax1, w);
            }
        }
        vmax0 = fmaxf(vmax0, __shfl_xor_sync(0xffffffffu, vmax0, 1));
        vmax0 = fmaxf(vmax0, __shfl_xor_sync(0xffffffffu, vmax0, 2));
        vmax1 = fmaxf(vmax1, __shfl_xor_sync(0xffffffffu, vmax1, 1));
        vmax1 = fmaxf(vmax1, __shfl_xor_sync(0xffffffffu, vmax1, 2));

        const float mn0 = fmaxf(m0, vmax0);
        const float mn1 = fmaxf(m1, vmax1);
        const float al0 = __expf(m0 - mn0);
        const float al1 = __expf(m1 - mn1);
        m0 = mn0; m1 = mn1;

        float sum0 = 0.f, sum1 = 0.f;
#pragma unroll
        for (int f = 0; f < 8; f++) {
            s[f][0] = __expf(s[f][0] - mn0); sum0 += s[f][0];
            s[f][1] = __expf(s[f][1] - mn0); sum0 += s[f][1];
            s[f][2] = __expf(s[f][2] - mn1); sum1 += s[f][2];
            s[f][3] = __expf(s[f][3] - mn1); sum1 += s[f][3];
        }
        sum0 += __shfl_xor_sync(0xffffffffu, sum0, 1);
        sum0 += __shfl_xor_sync(0xffffffffu, sum0, 2);
        sum1 += __shfl_xor_sync(0xffffffffu, sum1, 1);
        sum1 += __shfl_xor_sync(0xffffffffu, sum1, 2);
        l0 = l0 * al0 + sum0;
        l1 = l1 * al1 + sum1;

#pragma unroll
        for (int f = 0; f < 16; f++) {
            o[f][0] *= al0; o[f][1] *= al0;
            o[f][2] *= al1; o[f][3] *= al1;
        }

        // ---- O += P V ----
#pragma unroll
        for (int ks = 0; ks < 4; ks++) {
            uint32_t ah[4], alo[4];
            split2(s[2 * ks][0],     s[2 * ks][1],     ah[0], alo[0]);
            split2(s[2 * ks][2],     s[2 * ks][3],     ah[1], alo[1]);
            split2(s[2 * ks + 1][0], s[2 * ks + 1][1], ah[2], alo[2]);
            split2(s[2 * ks + 1][2], s[2 * ks + 1][3], ah[3], alo[3]);
            const int r = ks * 16 + (lane & 15);
#pragma unroll
            for (int ng = 0; ng < 8; ng++) {
                const int g = ng * 2 + (lane >> 4);
                const uint32_t off = base + 32768
                    + (uint32_t)(r * 256 + ((g ^ (r & 7)) << 4));
                uint32_t th[4], tl[4];
                ldsm4t(th, off);
                ldsm4t(tl, off + 16384);
                uint32_t bh0[2] = {th[0], th[1]}, bh1[2] = {th[2], th[3]};
                uint32_t bl0[2] = {tl[0], tl[1]}, bl1[2] = {tl[2], tl[3]};
                mma16816(o[2 * ng],     ah,  bh0);
                mma16816(o[2 * ng],     ah,  bl0);
                mma16816(o[2 * ng],     alo, bh0);
                mma16816(o[2 * ng + 1], ah,  bh1);
                mma16816(o[2 * ng + 1], ah,  bl1);
                mma16816(o[2 * ng + 1], alo, bh1);
            }
        }

        __syncthreads();
        if (kt + 2 <= ktmax) issue(kt + 2, kt & 1);
        CP_COMMIT();
    }

    // ---- finalize: write pre-split attn for proj GEMM ----
    const float inv0 = 1.f / l0;
    const float inv1 = 1.f / l1;
    uint32_t* Ah = (uint32_t*)g_Ahi;
    uint32_t* Al = (uint32_t*)g_Alo;
    const int colb = h * HD + 2 * (lane & 3);
#pragma unroll
    for (int f = 0; f < 16; f++) {
        uint32_t hi, lo;
        const int idx0 = (row0 * HID + colb + f * 8) >> 1;
        split2(o[f][0] * inv0, o[f][1] * inv0, hi, lo);
        Ah[idx0] = hi; Al[idx0] = lo;
        const int idx1 = ((row0 + 8) * HID + colb + f * 8) >> 1;
        split2(o[f][2] * inv1, o[f][3] * inv1, hi, lo);
        Ah[idx1] = hi; Al[idx1] = lo;
    }
}

// ========================= launch ===========================================
extern "C" void kernel_launch(void* const* d_in, const int* in_sizes, int n_in,
                              void* d_out, int out_size)
{
    (void)in_sizes; (void)n_in; (void)out_size;
    const int*   positions = (const int*)  d_in[0];
    const float* X         = (const float*)d_in[1];
    const float* Wqkv      = (const float*)d_in[2];
    const float* bqkv      = (const float*)d_in[3];
    const float* Wproj     = (const float*)d_in[4];
    const float* bproj     = (const float*)d_in[5];
    float* out = (float*)d_out;

    __nv_bfloat16 *xhi, *xlo, *wqhi, *wqlo, *wphi, *wplo, *ahi, *alo;
    cudaGetSymbolAddress((void**)&xhi,  g_Xhi);
    cudaGetSymbolAddress((void**)&xlo,  g_Xlo);
    cudaGetSymbolAddress((void**)&wqhi, g_Wq_hi);
    cudaGetSymbolAddress((void**)&wqlo, g_Wq_lo);
    cudaGetSymbolAddress((void**)&wphi, g_Wp_hi);
    cudaGetSymbolAddress((void**)&wplo, g_Wp_lo);
    cudaGetSymbolAddress((void**)&ahi,  g_Ahi);
    cudaGetSymbolAddress((void**)&alo,  g_Alo);

    // 1) RoPE tables + operand splits
    rope_table_kernel<<<(S_LEN * HALF + 255) / 256, 256>>>(positions);
    {
        int n4 = S_LEN * HID / 4;
        split_kernel<<<(n4 + 255) / 256, 256>>>((const float4*)X,
                                                (uint2*)xhi, (uint2*)xlo, n4);
    }
    {
        int n4 = HID * QKV_N / 4;
        split_kernel<<<(n4 + 255) / 256, 256>>>((const float4*)Wqkv,
                                                (uint2*)wqhi, (uint2*)wqlo, n4);
    }
    {
        int n4 = HID * HID / 4;
        split_kernel<<<(n4 + 255) / 256, 256>>>((const float4*)Wproj,
                                                (uint2*)wphi, (uint2*)wplo, n4);
    }

    // 2) QKV GEMM -> pre-split q/k/v
    cudaFuncSetAttribute(hmma_gemm2, cudaFuncAttributeMaxDynamicSharedMemorySize,
                         G2_SMEM);
    {
        dim3 grid(QKV_N / 256, S_LEN / 128);
        hmma_gemm2<<<grid, 512, G2_SMEM>>>(xhi, xlo, wqhi, wqlo, bqkv, nullptr,
                                           QKV_N, HID, 1);
    }

    // 3) Flash attention -> pre-split attn
    cudaFuncSetAttribute(flash_hmma, cudaFuncAttributeMaxDynamicSharedMemorySize,
                         FL_SMEM);
    {
        dim3 grid(S_LEN / 128, NH);
        flash_hmma<<<grid, 256, FL_SMEM>>>();
    }

    // 4) Output projection
    {
        dim3 grid(HID / 256, S_LEN / 128);
        hmma_gemm2<<<grid, 512, G2_SMEM>>>(ahi, alo, wphi, wplo, bproj, out,
                                           HID, HID, 0);
    }
}